// round 16
// baseline (speedup 1.0000x reference)
#include <cuda_runtime.h>
#include <cuda_bf16.h>
#include <math.h>
#include <cstdint>
#include <cstddef>

#define BATCH 32
#define TOK 257
#define NQ 8
#define DIM 1024
#define MX (BATCH*TOK)      /* 8224 */
#define ML (BATCH*NQ)       /* 256  */
#define HEADS 16
#define DHEAD 64
#define FFI 4096
#define EPS 1e-5f
#define NPAD 256            /* token dim for scores/U gemm (token 256 analytic) */
#define ADALD (8*4096)
#define SEG_S ((size_t)32*128*256)    /* scores partial plane stride */
#define USEG  ((size_t)32*128*1024)   /* U partial plane stride */

typedef __nv_bfloat16 bf16;

// ---------------- scratch (device globals) ----------------------------------
__device__ float g_temb[BATCH*DIM];
__device__ float g_h[MX*DIM];
__device__ float g_lat[ML*DIM];
__device__ float g_qkv[ML*3072];
__device__ float g_ada8[BATCH*8*4096];
__device__ float g_obuf[ML*DIM];
__device__ float g_part[(size_t)13*1024*1024];
__device__ float g_rowc[BATCH*128];
__device__ float g_s256[BATCH*128];
__device__ float g_w256[BATCH*128];
__device__ float g_swsum[BATCH*128];
__device__ float g_olat[BATCH*128*64];

// split bf16 buffers: [m][2K] = [hi(K) | lo(K)]
__device__ bf16 g_xs   [(size_t)MX*1536];
__device__ bf16 g_hns  [(size_t)MX*2048];
__device__ bf16 g_latms[ML*2048];
__device__ bf16 g_attns[ML*2048];
__device__ bf16 g_ffs  [ML*8192];
__device__ bf16 g_lats [ML*2048];
__device__ bf16 g_stembs[BATCH*2048];
__device__ bf16 g_psp  [(size_t)BATCH*128*2048];
__device__ bf16 g_wspl [(size_t)BATCH*128*(2*NPAD)];
__device__ bf16 g_hnT  [(size_t)BATCH*1024*(2*NPAD)];

// split bf16 transposed weights: [N][2K]
__device__ bf16 w_pi  [(size_t)1024*1536];
__device__ bf16 w_po  [(size_t)1024*2048];
__device__ bf16 w_qkvl[(size_t)8*3072*2048];
__device__ bf16 w_o   [(size_t)8*1024*2048];
__device__ bf16 w_ada [(size_t)8*4096*2048];
__device__ bf16 w_f1  [(size_t)8*4096*2048];
__device__ bf16 w_f2  [(size_t)8*1024*8192];

// ---------------- helpers ------------------------------------------------------
__device__ __forceinline__ float siluf(float x){ return x / (1.f + expf(-x)); }
__device__ __forceinline__ float geluf(float x){ return 0.5f * x * (1.f + erff(x * 0.70710678118654752f)); }

__device__ __forceinline__ uint32_t smem_u32(const void* p){
    uint32_t a;
    asm("{ .reg .u64 t; cvta.to.shared.u64 t, %1; cvt.u32.u64 %0, t; }" : "=r"(a) : "l"(p));
    return a;
}
#define SWZ(x) ((x) ^ (((x) >> 3) & 0x70))

__device__ __forceinline__ void ldsm4(uint32_t& r0, uint32_t& r1, uint32_t& r2, uint32_t& r3, uint32_t a){
    asm volatile("ldmatrix.sync.aligned.m8n8.x4.shared.b16 {%0,%1,%2,%3}, [%4];"
                 : "=r"(r0),"=r"(r1),"=r"(r2),"=r"(r3) : "r"(a));
}
__device__ __forceinline__ void mma16816(float* c, const uint32_t* a, uint32_t b0, uint32_t b1){
    asm volatile("mma.sync.aligned.m16n8k16.row.col.f32.bf16.bf16.f32 "
                 "{%0,%1,%2,%3}, {%4,%5,%6,%7}, {%8,%9}, {%0,%1,%2,%3};"
                 : "+f"(c[0]),"+f"(c[1]),"+f"(c[2]),"+f"(c[3])
                 : "r"(a[0]),"r"(a[1]),"r"(a[2]),"r"(a[3]), "r"(b0),"r"(b1));
}

#define ASTG (128*128)
#define BSTG (128*128)
#define STG  (ASTG+BSTG)
#define GEMM_SMEM (3*STG)       /* 96 KB, 3-stage -> 2 CTAs/SM */

// small-M kernel: 32x128 tile
#define ASTG2 (32*128)
#define BSTG2 (128*128)
#define STG2  (ASTG2+BSTG2)
#define S32_SMEM (3*STG2)       /* 60 KB, 3-stage -> 3 CTAs/SM */

// ======================= split-3 bf16 GEMM (128x128, split-K) ==================
__global__ void __launch_bounds__(256, 2) gemm_mma(
    const bf16* __restrict__ A, const bf16* __restrict__ Bt,
    const float* __restrict__ bias, float* __restrict__ C,
    float* __restrict__ part,
    int M, int N, int K, int cz, int act, int accum)
{
    extern __shared__ __align__(1024) char smem[];
    const uint32_t sb = smem_u32(smem);
    const int tid = threadIdx.x;
    const int wid = tid >> 5, lane = tid & 31;
    const int wm = wid & 3, wn = wid >> 2;

    const int m_base = blockIdx.y * 128;
    const int n_base = blockIdx.x * 128;
    const int cps = K >> 6;
    const int cbeg = blockIdx.z * cz;
    const size_t rstride = 2 * (size_t)K;

    const int ldrow = tid >> 3;
    const int ldc16 = tid & 7;

    auto load_chunk = [&](int t, int slot){
        int c = cbeg + t;
        if (t < cz) {
            int seg = c / cps, w = c - seg * cps;
            int aoff = ((seg == 2) ? K : 0) + w * 64;
            int boff = ((seg == 1) ? K : 0) + w * 64;
            uint32_t ab = sb + (uint32_t)slot * STG;
            uint32_t bb = ab + ASTG;
            #pragma unroll
            for (int i = 0; i < 4; i++) {
                int row = ldrow + i * 32;
                int gm = m_base + row;
                int sz = (gm < M) ? 16 : 0;
                if (gm >= M) gm = 0;
                const bf16* srcA = A + (size_t)gm * rstride + aoff + ldc16 * 8;
                asm volatile("cp.async.cg.shared.global [%0], [%1], 16, %2;"
                             :: "r"(ab + SWZ(row * 128 + ldc16 * 16)), "l"(srcA), "r"(sz));
                const bf16* srcB = Bt + (size_t)(n_base + row) * rstride + boff + ldc16 * 8;
                asm volatile("cp.async.cg.shared.global [%0], [%1], 16;"
                             :: "r"(bb + SWZ(row * 128 + ldc16 * 16)), "l"(srcB));
            }
        }
        asm volatile("cp.async.commit_group;" ::: "memory");
    };

    float acc[2][8][4];
    #pragma unroll
    for (int i = 0; i < 2; i++)
        #pragma unroll
        for (int j = 0; j < 8; j++)
            #pragma unroll
            for (int k = 0; k < 4; k++) acc[i][j][k] = 0.f;

    const int lrow = lane & 15;
    const int lhi  = (lane >> 4) & 1;
    uint32_t a_ro[2], a_rx[2], b_ro[4], b_rx[4];
    #pragma unroll
    for (int f = 0; f < 2; f++) {
        int r = wm * 32 + f * 16 + lrow;
        a_ro[f] = r * 128; a_rx[f] = ((r & 7) << 4);
    }
    #pragma unroll
    for (int g = 0; g < 4; g++) {
        int r = wn * 64 + g * 16 + lrow;
        b_ro[g] = r * 128; b_rx[g] = ((r & 7) << 4);
    }
    const uint32_t cb0 = lhi * 16;

    load_chunk(0, 0); load_chunk(1, 1);
    int sl = 0;

    for (int t = 0; t < cz; t++) {
        asm volatile("cp.async.wait_group 1;" ::: "memory");
        __syncthreads();
        int nsl = sl + 2; if (nsl >= 3) nsl -= 3;
        load_chunk(t + 2, nsl);
        uint32_t ab = sb + (uint32_t)sl * STG;
        uint32_t bb = ab + ASTG;
        #pragma unroll
        for (int ks = 0; ks < 4; ks++) {
            uint32_t cbyte = cb0 + ks * 32;
            uint32_t ra[2][4], rb[4][4];
            #pragma unroll
            for (int f = 0; f < 2; f++)
                ldsm4(ra[f][0], ra[f][1], ra[f][2], ra[f][3], ab + a_ro[f] + (cbyte ^ a_rx[f]));
            #pragma unroll
            for (int g = 0; g < 4; g++)
                ldsm4(rb[g][0], rb[g][1], rb[g][2], rb[g][3], bb + b_ro[g] + (cbyte ^ b_rx[g]));
            #pragma unroll
            for (int mt = 0; mt < 2; mt++)
                #pragma unroll
                for (int g = 0; g < 4; g++) {
                    mma16816(acc[mt][2*g],   ra[mt], rb[g][0], rb[g][2]);
                    mma16816(acc[mt][2*g+1], ra[mt], rb[g][1], rb[g][3]);
                }
        }
        sl = (sl + 1 == 3) ? 0 : sl + 1;
    }

    const int g4 = lane >> 2, t4 = lane & 3;
    const bool direct = (gridDim.z == 1);
    #pragma unroll
    for (int mt = 0; mt < 2; mt++) {
        #pragma unroll
        for (int r2 = 0; r2 < 2; r2++) {
            int gm = m_base + wm * 32 + mt * 16 + r2 * 8 + g4;
            if (gm >= M) continue;
            #pragma unroll
            for (int nt = 0; nt < 8; nt++) {
                int gn = n_base + wn * 64 + nt * 8 + t4 * 2;
                float v0 = acc[mt][nt][r2 * 2 + 0];
                float v1 = acc[mt][nt][r2 * 2 + 1];
                if (direct) {
                    if (bias) { v0 += bias[gn]; v1 += bias[gn + 1]; }
                    if (act)  { v0 = geluf(v0); v1 = geluf(v1); }
                    float* cp = C + (size_t)gm * N + gn;
                    if (accum) { cp[0] += v0; cp[1] += v1; }
                    else       { *reinterpret_cast<float2*>(cp) = make_float2(v0, v1); }
                } else {
                    float* pp = part + ((size_t)blockIdx.z * M + gm) * N + gn;
                    *reinterpret_cast<float2*>(pp) = make_float2(v0, v1);
                }
            }
        }
    }
}

// ============ small-M split-3 GEMM: 32x128 tile, partials only =================
__global__ void __launch_bounds__(256, 3) gemm_s32(
    const bf16* __restrict__ A, const bf16* __restrict__ Bt,
    float* __restrict__ part, int N, int K, int cz)
{
    extern __shared__ __align__(1024) char smem[];
    const uint32_t sb = smem_u32(smem);
    const int tid = threadIdx.x;
    const int wid = tid >> 5, lane = tid & 31;
    const int wn = wid;

    const int n_base = blockIdx.x * 128;
    const int cps = K >> 6;
    const int cbeg = blockIdx.z * cz;
    const size_t rstride = 2 * (size_t)K;

    const int ldrow = tid >> 3;
    const int ldc16 = tid & 7;

    auto load_chunk = [&](int t, int slot){
        int c = cbeg + t;
        if (t < cz) {
            int seg = c / cps, w = c - seg * cps;
            int aoff = ((seg == 2) ? K : 0) + w * 64;
            int boff = ((seg == 1) ? K : 0) + w * 64;
            uint32_t ab = sb + (uint32_t)slot * STG2;
            uint32_t bb = ab + ASTG2;
            {
                const bf16* srcA = A + (size_t)(ldrow & 31) * rstride + aoff + ldc16 * 8;
                if (ldrow < 32)
                    asm volatile("cp.async.cg.shared.global [%0], [%1], 16;"
                                 :: "r"(ab + SWZ(ldrow * 128 + ldc16 * 16)), "l"(srcA));
            }
            #pragma unroll
            for (int i = 0; i < 4; i++) {
                int row = ldrow + i * 32;
                const bf16* srcB = Bt + (size_t)(n_base + row) * rstride + boff + ldc16 * 8;
                asm volatile("cp.async.cg.shared.global [%0], [%1], 16;"
                             :: "r"(bb + SWZ(row * 128 + ldc16 * 16)), "l"(srcB));
            }
        }
        asm volatile("cp.async.commit_group;" ::: "memory");
    };

    float acc[2][2][4];
    #pragma unroll
    for (int i = 0; i < 2; i++)
        #pragma unroll
        for (int j = 0; j < 2; j++)
            #pragma unroll
            for (int k = 0; k < 4; k++) acc[i][j][k] = 0.f;

    const int lrow = lane & 15;
    const int lhi  = (lane >> 4) & 1;
    uint32_t a_ro[2], a_rx[2], b_ro, b_rx;
    #pragma unroll
    for (int f = 0; f < 2; f++) {
        int r = f * 16 + lrow;
        a_ro[f] = r * 128; a_rx[f] = ((r & 7) << 4);
    }
    {
        int r = wn * 16 + lrow;
        b_ro = r * 128; b_rx = ((r & 7) << 4);
    }
    const uint32_t cb0 = lhi * 16;

    load_chunk(0, 0); load_chunk(1, 1);
    int sl = 0;

    for (int t = 0; t < cz; t++) {
        asm volatile("cp.async.wait_group 1;" ::: "memory");
        __syncthreads();
        int nsl = sl + 2; if (nsl >= 3) nsl -= 3;
        load_chunk(t + 2, nsl);
        uint32_t ab = sb + (uint32_t)sl * STG2;
        uint32_t bb = ab + ASTG2;
        #pragma unroll
        for (int ks = 0; ks < 4; ks++) {
            uint32_t cbyte = cb0 + ks * 32;
            uint32_t ra[2][4], rb[4];
            #pragma unroll
            for (int f = 0; f < 2; f++)
                ldsm4(ra[f][0], ra[f][1], ra[f][2], ra[f][3], ab + a_ro[f] + (cbyte ^ a_rx[f]));
            ldsm4(rb[0], rb[1], rb[2], rb[3], bb + b_ro + (cbyte ^ b_rx));
            #pragma unroll
            for (int mt = 0; mt < 2; mt++) {
                mma16816(acc[mt][0], ra[mt], rb[0], rb[2]);
                mma16816(acc[mt][1], ra[mt], rb[1], rb[3]);
            }
        }
        sl = (sl + 1 == 3) ? 0 : sl + 1;
    }

    const int g4 = lane >> 2, t4 = lane & 3;
    #pragma unroll
    for (int mt = 0; mt < 2; mt++) {
        #pragma unroll
        for (int r2 = 0; r2 < 2; r2++) {
            int gm = mt * 16 + r2 * 8 + g4;
            #pragma unroll
            for (int nt = 0; nt < 2; nt++) {
                int gn = n_base + wn * 16 + nt * 8 + t4 * 2;
                float v0 = acc[mt][nt][r2 * 2 + 0];
                float v1 = acc[mt][nt][r2 * 2 + 1];
                float* pp = part + ((size_t)blockIdx.z * 32 + gm) * N + gn;
                *reinterpret_cast<float2*>(pp) = make_float2(v0, v1);
            }
        }
    }
}

// ============ batched split-3 GEMM (blockIdx.z = batch) ========================
// If gridDim.y > 1, blockIdx.y = segment (0..2): each CTA computes ONE of the
// 3 split-3 segments, writing to C + seg*sSeg (partial planes; consumer sums).
__global__ void __launch_bounds__(256, 2) gemm_bat(
    const bf16* __restrict__ A, const bf16* __restrict__ Bt, float* __restrict__ C,
    int N, int K, int ldc, size_t sA, size_t sB, size_t sC, size_t sSeg)
{
    extern __shared__ __align__(1024) char smem[];
    const uint32_t sb = smem_u32(smem);
    const int tid = threadIdx.x;
    const int wid = tid >> 5, lane = tid & 31;
    const int wm = wid & 3, wn = wid >> 2;
    const int bat = blockIdx.z;
    A  += (size_t)bat * sA;
    Bt += (size_t)bat * sB;
    C  += (size_t)bat * sC + (size_t)blockIdx.y * sSeg;

    const int n_base = blockIdx.x * 128;
    const int cps = K >> 6;
    const int cbeg = (gridDim.y > 1) ? (int)blockIdx.y * cps : 0;
    const int cz   = (gridDim.y > 1) ? cps : 3 * cps;
    const size_t rstride = 2 * (size_t)K;

    const int ldrow = tid >> 3;
    const int ldc16 = tid & 7;

    auto load_chunk = [&](int t, int slot){
        if (t < cz) {
            int c = cbeg + t;
            int seg = c / cps, w = c - seg * cps;
            int aoff = ((seg == 2) ? K : 0) + w * 64;
            int boff = ((seg == 1) ? K : 0) + w * 64;
            uint32_t ab = sb + (uint32_t)slot * STG;
            uint32_t bb = ab + ASTG;
            #pragma unroll
            for (int i = 0; i < 4; i++) {
                int row = ldrow + i * 32;
                const bf16* srcA = A + (size_t)row * rstride + aoff + ldc16 * 8;
                asm volatile("cp.async.cg.shared.global [%0], [%1], 16;"
                             :: "r"(ab + SWZ(row * 128 + ldc16 * 16)), "l"(srcA));
                const bf16* srcB = Bt + (size_t)(n_base + row) * rstride + boff + ldc16 * 8;
                asm volatile("cp.async.cg.shared.global [%0], [%1], 16;"
                             :: "r"(bb + SWZ(row * 128 + ldc16 * 16)), "l"(srcB));
            }
        }
        asm volatile("cp.async.commit_group;" ::: "memory");
    };

    float acc[2][8][4];
    #pragma unroll
    for (int i = 0; i < 2; i++)
        #pragma unroll
        for (int j = 0; j < 8; j++)
            #pragma unroll
            for (int k = 0; k < 4; k++) acc[i][j][k] = 0.f;

    const int lrow = lane & 15;
    const int lhi  = (lane >> 4) & 1;
    uint32_t a_ro[2], a_rx[2], b_ro[4], b_rx[4];
    #pragma unroll
    for (int f = 0; f < 2; f++) {
        int r = wm * 32 + f * 16 + lrow;
        a_ro[f] = r * 128; a_rx[f] = ((r & 7) << 4);
    }
    #pragma unroll
    for (int g = 0; g < 4; g++) {
        int r = wn * 64 + g * 16 + lrow;
        b_ro[g] = r * 128; b_rx[g] = ((r & 7) << 4);
    }
    const uint32_t cb0 = lhi * 16;

    load_chunk(0, 0); load_chunk(1, 1);
    int sl = 0;

    for (int t = 0; t < cz; t++) {
        asm volatile("cp.async.wait_group 1;" ::: "memory");
        __syncthreads();
        int nsl = sl + 2; if (nsl >= 3) nsl -= 3;
        load_chunk(t + 2, nsl);
        uint32_t ab = sb + (uint32_t)sl * STG;
        uint32_t bb = ab + ASTG;
        #pragma unroll
        for (int ks = 0; ks < 4; ks++) {
            uint32_t cbyte = cb0 + ks * 32;
            uint32_t ra[2][4], rb[4][4];
            #pragma unroll
            for (int f = 0; f < 2; f++)
                ldsm4(ra[f][0], ra[f][1], ra[f][2], ra[f][3], ab + a_ro[f] + (cbyte ^ a_rx[f]));
            #pragma unroll
            for (int g = 0; g < 4; g++)
                ldsm4(rb[g][0], rb[g][1], rb[g][2], rb[g][3], bb + b_ro[g] + (cbyte ^ b_rx[g]));
            #pragma unroll
            for (int mt = 0; mt < 2; mt++)
                #pragma unroll
                for (int g = 0; g < 4; g++) {
                    mma16816(acc[mt][2*g],   ra[mt], rb[g][0], rb[g][2]);
                    mma16816(acc[mt][2*g+1], ra[mt], rb[g][1], rb[g][3]);
                }
        }
        sl = (sl + 1 == 3) ? 0 : sl + 1;
    }

    const int g4 = lane >> 2, t4 = lane & 3;
    #pragma unroll
    for (int mt = 0; mt < 2; mt++) {
        #pragma unroll
        for (int r2 = 0; r2 < 2; r2++) {
            int gm = wm * 32 + mt * 16 + r2 * 8 + g4;
            #pragma unroll
            for (int nt = 0; nt < 8; nt++) {
                int gn = n_base + wn * 64 + nt * 8 + t4 * 2;
                float v0 = acc[mt][nt][r2 * 2 + 0];
                float v1 = acc[mt][nt][r2 * 2 + 1];
                *reinterpret_cast<float2*>(C + (size_t)gm * ldc + gn) = make_float2(v0, v1);
            }
        }
    }
}

// ---------------- split-K reduce + epilogue (float4) ---------------------------
__global__ void reduce_ep4(const float* __restrict__ part, const float* __restrict__ bias,
                           float* __restrict__ C, bf16* __restrict__ outs,
                           int MN4, int N, int S, int act, int accum)
{
    int i4 = blockIdx.x * 256 + threadIdx.x;
    if (i4 >= MN4) return;
    size_t base = (size_t)i4 * 4;
    int m = (int)(base / N), n = (int)(base % N);
    float4 s = make_float4(0.f, 0.f, 0.f, 0.f);
    for (int t = 0; t < S; t++) {
        float4 p = reinterpret_cast<const float4*>(part)[(size_t)t * MN4 + i4];
        s.x += p.x; s.y += p.y; s.z += p.z; s.w += p.w;
    }
    if (bias) {
        float4 bb = reinterpret_cast<const float4*>(bias)[n >> 2];
        s.x += bb.x; s.y += bb.y; s.z += bb.z; s.w += bb.w;
    }
    if (act) { s.x = geluf(s.x); s.y = geluf(s.y); s.z = geluf(s.z); s.w = geluf(s.w); }
    if (C) {
        if (accum) {
            float4 c = reinterpret_cast<float4*>(C)[i4];
            s.x += c.x; s.y += c.y; s.z += c.z; s.w += c.w;
        }
        reinterpret_cast<float4*>(C)[i4] = s;
    }
    if (outs) {
        float y[4] = {s.x, s.y, s.z, s.w};
        union { bf16 b[4]; uint2 u; } hi, lo;
        #pragma unroll
        for (int j = 0; j < 4; j++) {
            bf16 h = __float2bfloat16(y[j]);
            hi.b[j] = h; lo.b[j] = __float2bfloat16(y[j] - __bfloat162float(h));
        }
        *reinterpret_cast<uint2*>(outs + (size_t)m * 2 * N + n)     = hi.u;
        *reinterpret_cast<uint2*>(outs + (size_t)m * 2 * N + N + n) = lo.u;
    }
}

// ---------------- block reduction helper ----------------------------------------
__device__ __forceinline__ void block_reduce2(float& s1, float& s2,
                                              float* sh1, float* sh2, int tid)
{
    #pragma unroll
    for (int o = 16; o > 0; o >>= 1) {
        s1 += __shfl_xor_sync(0xffffffffu, s1, o);
        s2 += __shfl_xor_sync(0xffffffffu, s2, o);
    }
    int w = tid >> 5, lane = tid & 31;
    if (lane == 0) { sh1[w] = s1; sh2[w] = s2; }
    __syncthreads();
    if (tid < 32) {
        float a = (tid < 8) ? sh1[tid] : 0.f;
        float c = (tid < 8) ? sh2[tid] : 0.f;
        #pragma unroll
        for (int o = 4; o > 0; o >>= 1) {
            a += __shfl_xor_sync(0xffffffffu, a, o);
            c += __shfl_xor_sync(0xffffffffu, c, o);
        }
        if (tid == 0) { sh1[0] = a; sh2[0] = c; }
    }
    __syncthreads();
    s1 = sh1[0]; s2 = sh2[0];
}

// ------ fused: split-K reduce + residual into lat + LN(+adaLN) -> split bf16 ----
__global__ void reduce_ln(const float* __restrict__ part, int S,
                          float* __restrict__ lat, bf16* __restrict__ outs,
                          const float* __restrict__ gamma, const float* __restrict__ beta,
                          const float* __restrict__ adap, int shift_off, int scale_off)
{
    int r = blockIdx.x, b = r >> 3, tid = threadIdx.x;
    __shared__ float sh1[8], sh2[8];
    const size_t MN4 = (size_t)ML * 256;
    size_t i4 = (size_t)r * 256 + tid;
    float4 v = reinterpret_cast<float4*>(lat)[i4];
    for (int t = 0; t < S; t++) {
        float4 p = reinterpret_cast<const float4*>(part)[(size_t)t * MN4 + i4];
        v.x += p.x; v.y += p.y; v.z += p.z; v.w += p.w;
    }
    reinterpret_cast<float4*>(lat)[i4] = v;
    float y[4] = {v.x, v.y, v.z, v.w};
    if (gamma) {
        float s1 = v.x + v.y + v.z + v.w;
        float s2 = v.x*v.x + v.y*v.y + v.z*v.z + v.w*v.w;
        block_reduce2(s1, s2, sh1, sh2, tid);
        float mean = s1 * (1.f / DIM);
        float var  = s2 * (1.f / DIM) - mean * mean;
        float inv  = rsqrtf(var + EPS);
        float4 g  = reinterpret_cast<const float4*>(gamma)[tid];
        float4 be = reinterpret_cast<const float4*>(beta)[tid];
        float4 sc = reinterpret_cast<const float4*>(adap + (size_t)b * ADALD + scale_off)[tid];
        float4 sf = reinterpret_cast<const float4*>(adap + (size_t)b * ADALD + shift_off)[tid];
        float gg[4]  = {g.x, g.y, g.z, g.w};
        float bb[4]  = {be.x, be.y, be.z, be.w};
        float scc[4] = {sc.x, sc.y, sc.z, sc.w};
        float sff[4] = {sf.x, sf.y, sf.z, sf.w};
        #pragma unroll
        for (int j = 0; j < 4; j++)
            y[j] = ((y[j] - mean) * inv * gg[j] + bb[j]) * (1.f + scc[j]) + sff[j];
    }
    union { bf16 b4[4]; uint2 u; } hi, lo;
    #pragma unroll
    for (int j = 0; j < 4; j++) {
        bf16 h = __float2bfloat16(y[j]);
        hi.b4[j] = h; lo.b4[j] = __float2bfloat16(y[j] - __bfloat162float(h));
    }
    int k0 = tid * 4;
    *reinterpret_cast<uint2*>(outs + (size_t)r * 2048 + k0)        = hi.u;
    *reinterpret_cast<uint2*>(outs + (size_t)r * 2048 + 1024 + k0) = lo.u;
}

// ---------------- conversions (vectorized) ---------------------------------------
__global__ void convert_a(const float* __restrict__ in, bf16* __restrict__ out, int K)
{
    size_t i4 = (size_t)blockIdx.x * 256 + threadIdx.x;
    size_t base = i4 * 4;
    int k = (int)(base % K);
    size_t m = base / K;
    float4 v = reinterpret_cast<const float4*>(in)[i4];
    float y[4] = {v.x, v.y, v.z, v.w};
    union { bf16 b[4]; uint2 u; } hi, lo;
    #pragma unroll
    for (int j = 0; j < 4; j++) {
        bf16 h = __float2bfloat16(y[j]);
        hi.b[j] = h; lo.b[j] = __float2bfloat16(y[j] - __bfloat162float(h));
    }
    *reinterpret_cast<uint2*>(out + m * 2 * K + k)     = hi.u;
    *reinterpret_cast<uint2*>(out + m * 2 * K + K + k) = lo.u;
}

// W [K][N] fp32 -> T [N][2K] split bf16; 64k x 32n tiles, 16B stores
__global__ void wsplit_t(const float* __restrict__ W, bf16* __restrict__ T,
                         int K, int N, size_t wStride, size_t tStride)
{
    __shared__ float tile[64][33];
    int l = blockIdx.z;
    W += (size_t)l * wStride;
    T += (size_t)l * tStride;
    int n0 = blockIdx.x * 32, k0 = blockIdx.y * 64;
    int c = threadIdx.x & 31, r0 = threadIdx.x >> 5;
    #pragma unroll
    for (int i = 0; i < 8; i++)
        tile[r0 + i * 8][c] = W[(size_t)(k0 + r0 + i * 8) * N + n0 + c];
    __syncthreads();
    int nn = threadIdx.x >> 3;
    int kg = (threadIdx.x & 7) * 8;
    union { bf16 b[8]; uint4 u; } hi, lo;
    #pragma unroll
    for (int j = 0; j < 8; j++) {
        float v = tile[kg + j][nn];
        bf16 h = __float2bfloat16(v);
        hi.b[j] = h; lo.b[j] = __float2bfloat16(v - __bfloat162float(h));
    }
    size_t n = n0 + nn;
    *reinterpret_cast<uint4*>(T + n * 2 * K + k0 + kg)     = hi.u;
    *reinterpret_cast<uint4*>(T + n * 2 * K + K + k0 + kg) = lo.u;
}

// ---------------- hn transpose (per batch): hnT[b][c][2*NPAD], tokens 0..255 ----
__global__ void hnt_kernel()
{
    __shared__ bf16 th[32][33], tl[32][33];
    int b = blockIdx.z;
    int n0 = blockIdx.x * 32;
    int c0 = blockIdx.y * 32;
    int tx = threadIdx.x & 31, ty = threadIdx.x >> 5;
    #pragma unroll
    for (int i = 0; i < 4; i++) {
        int n = n0 + ty + i * 8;
        const bf16* r = g_hns + ((size_t)(b * TOK + n)) * 2048;
        th[ty + i * 8][tx] = r[c0 + tx];
        tl[ty + i * 8][tx] = r[1024 + c0 + tx];
    }
    __syncthreads();
    #pragma unroll
    for (int i = 0; i < 4; i++) {
        int cc = c0 + ty + i * 8;
        int n = n0 + tx;
        bf16* o = g_hnT + ((size_t)b * 1024 + cc) * (2 * NPAD);
        o[n]        = th[tx][ty + i * 8];
        o[NPAD + n] = tl[tx][ty + i * 8];
    }
}

// ---------------- P projection (+ fused fp32 score for token 256) ----------------
__global__ void pproj_kernel(const float* __restrict__ wkv_i,
                             const float* __restrict__ n1g, const float* __restrict__ n1b)
{
    __shared__ float sq[8][64];
    __shared__ float swk[32][65];
    int bh = blockIdx.x; int b = bh >> 4, h = bh & 15;
    int tid = threadIdx.x;
    for (int i = tid; i < 512; i += 256) {
        int l = i >> 6, d = i & 63;
        sq[l][d] = g_qkv[((size_t)(b * 8 + l)) * 3072 + h * 64 + d] * 0.125f;
    }
    int lq = tid >> 5;
    int cl = tid & 31;
    float rcacc = 0.f, s256acc = 0.f;
    const bf16* h256 = g_hns + ((size_t)(b * TOK + 256)) * 2048;
    bf16* pr = g_psp + ((size_t)b * 128 + h * 8 + lq) * 2048;
    for (int c0 = 0; c0 < 1024; c0 += 32) {
        __syncthreads();
        for (int i = tid; i < 32 * 64; i += 256) {
            int cc = i >> 6, d = i & 63;
            swk[cc][d] = wkv_i[(size_t)(c0 + cc) * 2048 + h * 64 + d];
        }
        __syncthreads();
        float acc = 0.f;
        #pragma unroll 16
        for (int d = 0; d < 64; d++) acc += sq[lq][d] * swk[cl][d];
        int cc = c0 + cl;
        rcacc += acc * n1b[cc];
        float pg = acc * n1g[cc];
        float hv = __bfloat162float(h256[cc]) + __bfloat162float(h256[1024 + cc]);
        s256acc += pg * hv;
        bf16 hi = __float2bfloat16(pg);
        pr[cc] = hi;
        pr[1024 + cc] = __float2bfloat16(pg - __bfloat162float(hi));
    }
    #pragma unroll
    for (int o = 16; o; o >>= 1) {
        rcacc   += __shfl_xor_sync(0xffffffffu, rcacc, o);
        s256acc += __shfl_xor_sync(0xffffffffu, s256acc, o);
    }
    if (cl == 0) {
        g_rowc[b * 128 + h * 8 + lq] = rcacc;
        g_s256[b * 128 + h * 8 + lq] = s256acc;
    }
}

// -------- softmax: 256 gemm'd tokens + analytic token 256 + latent kv ------------
__global__ void softmax_kernel()
{
    int bh = blockIdx.x; int b = bh >> 4, h = bh & 15;
    int l = threadIdx.x >> 5, lane = threadIdx.x & 31;
    int row = h * 8 + l;
    const float* sc0 = g_part + ((size_t)b * 128 + row) * 256;
    const float* sc1 = sc0 + SEG_S;
    const float* sc2 = sc1 + SEG_S;
    float rc = g_rowc[b * 128 + row];
    float v[8];
    #pragma unroll
    for (int j = 0; j < 8; j++) {
        int n = lane + j * 32;
        v[j] = sc0[n] + sc1[n] + sc2[n] + rc;
    }
    float s256 = g_s256[b * 128 + row] + rc;
    float lv = -1e30f;
    if (lane < 8) {
        const float* qp = g_qkv + ((size_t)(b * 8 + l))    * 3072 + h * 64;
        const float* kp = g_qkv + ((size_t)(b * 8 + lane)) * 3072 + 1024 + h * 64;
        float s = 0.f;
        #pragma unroll 16
        for (int d = 0; d < 64; d++) s += qp[d] * kp[d];
        lv = s * 0.125f;
    }
    float m = fmaxf(s256, lv);
    #pragma unroll
    for (int j = 0; j < 8; j++) m = fmaxf(m, v[j]);
    #pragma unroll
    for (int o = 16; o; o >>= 1) m = fmaxf(m, __shfl_xor_sync(0xffffffffu, m, o));
    float sum8 = 0.f;
    #pragma unroll
    for (int j = 0; j < 8; j++) {
        v[j] = expf(v[j] - m);
        sum8 += v[j];
    }
    float e256 = expf(s256 - m);
    float le = (lane < 8) ? expf(lv - m) : 0.f;
    float both = sum8 + le;
    float toks = sum8;
    #pragma unroll
    for (int o = 16; o; o >>= 1) {
        both += __shfl_xor_sync(0xffffffffu, both, o);
        toks += __shfl_xor_sync(0xffffffffu, toks, o);
    }
    float inv = 1.f / (both + e256);
    if (lane == 0) {
        g_swsum[b * 128 + row] = (toks + e256) * inv;
        g_w256[b * 128 + row]  = e256 * inv;
    }

    bf16* wr = g_wspl + ((size_t)b * 128 + row) * (2 * NPAD);
    #pragma unroll
    for (int j = 0; j < 8; j++) {
        int n = lane + j * 32;
        float w = v[j] * inv;
        bf16 hi = __float2bfloat16(w);
        wr[n]        = hi;
        wr[NPAD + n] = __float2bfloat16(w - __bfloat162float(hi));
    }
    float myle = le * inv;
    float wl[8];
    #pragma unroll
    for (int n = 0; n < 8; n++) wl[n] = __shfl_sync(0xffffffffu, myle, n);
    const float* vb = g_qkv + ((size_t)(b * 8)) * 3072 + 2048 + h * 64;
    float a0 = 0.f, a1 = 0.f;
    #pragma unroll
    for (int n = 0; n < 8; n++) {
        const float* vp = vb + (size_t)n * 3072;
        a0 += wl[n] * vp[lane];
        a1 += wl[n] * vp[lane + 32];
    }
    float* op = g_olat + ((size_t)b * 128 + row) * 64;
    op[lane] = a0; op[lane + 32] = a1;
}

// ------- out projection: sums 3 U partial planes + rank-1 token-256 update -------
__global__ void oproj_kernel(const float* __restrict__ wkv_i,
                             const float* __restrict__ n1g, const float* __restrict__ n1b)
{
    __shared__ float ut[8][1024];
    int bh = blockIdx.x; int b = bh >> 4, h = bh & 15;
    int tid = threadIdx.x;
    const bf16* h256 = g_hns + ((size_t)(b * TOK + 256)) * 2048;
    for (int i = tid; i < 8 * 1024; i += 256) {
        int l = i >> 10, c = i & 1023;
        int row = h * 8 + l;
        float hv = __bfloat162float(h256[c]) + __bfloat162float(h256[1024 + c]);
        size_t idx = ((size_t)b * 128 + row) * 1024 + c;
        float u = g_part[idx] + g_part[idx + USEG] + g_part[idx + 2 * USEG]
                + g_w256[b * 128 + row] * hv;
        ut[l][c] = u * n1g[c] + g_swsum[b * 128 + row] * n1b[c];
    }
    __syncthreads();
    int l = tid >> 5, lane = tid & 31;
    int row = h * 8 + l;
    float a0 = g_olat[((size_t)b * 128 + row) * 64 + lane];
    float a1 = g_olat[((size_t)b * 128 + row) * 64 + lane + 32];
    const float* wv = wkv_i + 1024 + h * 64;
    #pragma unroll 4
    for (int c = 0; c < 1024; c++) {
        float u = ut[l][c];
        a0 += u * wv[(size_t)c * 2048 + lane];
        a1 += u * wv[(size_t)c * 2048 + lane + 32];
    }
    size_t m = (size_t)(b * 8 + l);
    bf16* ar = g_attns + m * 2048;
    int d0 = h * 64 + lane, d1 = d0 + 32;
    bf16 h0 = __float2bfloat16(a0);
    ar[d0] = h0; ar[1024 + d0] = __float2bfloat16(a0 - __bfloat162float(h0));
    bf16 h1 = __float2bfloat16(a1);
    ar[d1] = h1; ar[1024 + d1] = __float2bfloat16(a1 - __bfloat162float(h1));
}

// ---------------- timestep embedding + time MLP -------------------------------------
__global__ void time_mlp_kernel(const int* __restrict__ ts,
    const float* __restrict__ w1, const float* __restrict__ b1,
    const float* __restrict__ w2, const float* __restrict__ b2)
{
    __shared__ float s_emb[320];
    __shared__ float s_hid[1024];
    int b = blockIdx.x, t = threadIdx.x;
    if (t < 160) {
        double f   = exp(-9.210340371976184 * (double)t / 160.0);
        double arg = (double)ts[b] * f;
        s_emb[t]       = (float)cos(arg);
        s_emb[t + 160] = (float)sin(arg);
    }
    __syncthreads();
    float acc = b1[t];
    for (int k = 0; k < 320; k++) acc += s_emb[k] * w1[k * 1024 + t];
    s_hid[t] = siluf(acc);
    __syncthreads();
    float acc2 = b2[t];
    for (int k = 0; k < 1024; k++) acc2 += s_hid[k] * w2[k * 1024 + t];
    g_temb[b * 1024 + t] = acc2;
    float sv = siluf(acc2);
    bf16 h = __float2bfloat16(sv);
    g_stembs[b * 2048 + t]        = h;
    g_stembs[b * 2048 + 1024 + t] = __float2bfloat16(sv - __bfloat162float(h));
}

// ---------------- hn = LN(h + bias + temb) -> split bf16 ----------------------------
__global__ void ln_h_kernel(const float* __restrict__ pib)
{
    int r = blockIdx.x;
    int b = r / TOK;
    int tid = threadIdx.x;
    __shared__ float sh1[8], sh2[8];
    const float* hrow = g_h + (size_t)r * DIM;
    const float* trow = g_temb + b * DIM;
    float v[4]; float s1 = 0.f, s2 = 0.f;
    #pragma unroll
    for (int j = 0; j < 4; j++) {
        int k = tid + j * 256;
        float t = hrow[k] + pib[k] + trow[k];
        v[j] = t; s1 += t; s2 += t * t;
    }
    block_reduce2(s1, s2, sh1, sh2, tid);
    float mean = s1 * (1.f / DIM);
    float var  = s2 * (1.f / DIM) - mean * mean;
    float inv  = rsqrtf(var + EPS);
    bf16* out = g_hns + (size_t)r * 2048;
    #pragma unroll
    for (int j = 0; j < 4; j++) {
        int k = tid + j * 256;
        float y = (v[j] - mean) * inv;
        bf16 h = __float2bfloat16(y);
        out[k]        = h;
        out[1024 + k] = __float2bfloat16(y - __bfloat162float(h));
    }
}

// ---------------- LN (+adaLN) -> split bf16 / fp32 ----------------------------------
__global__ void ln_mod_kernel(const float* __restrict__ in,
    float* __restrict__ outf, bf16* __restrict__ outs,
    const float* __restrict__ gamma, const float* __restrict__ beta,
    const float* __restrict__ ada, int ada_ld, int shift_off, int scale_off)
{
    int r = blockIdx.x;
    int b = r >> 3;
    int tid = threadIdx.x;
    __shared__ float sh1[8], sh2[8];
    const float* row = in + (size_t)r * DIM;
    float v[4]; float s1 = 0.f, s2 = 0.f;
    #pragma unroll
    for (int j = 0; j < 4; j++) {
        int k = tid + j * 256;
        float t = row[k];
        v[j] = t; s1 += t; s2 += t * t;
    }
    block_reduce2(s1, s2, sh1, sh2, tid);
    float mean = s1 * (1.f / DIM);
    float var  = s2 * (1.f / DIM) - mean * mean;
    float inv  = rsqrtf(var + EPS);
    #pragma unroll
    for (int j = 0; j < 4; j++) {
        int k = tid + j * 256;
        float y = (v[j] - mean) * inv * gamma[k] + beta[k];
        if (ada) y = y * (1.f + ada[(size_t)b * ada_ld + scale_off + k])
                    + ada[(size_t)b * ada_ld + shift_off + k];
        if (outf) outf[(size_t)r * DIM + k] = y;
        if (outs) {
            bf16 h = __float2bfloat16(y);
            outs[(size_t)r * 2048 + k]        = h;
            outs[(size_t)r * 2048 + 1024 + k] = __float2bfloat16(y - __bfloat162float(h));
        }
    }
}

// ---------------- latent init ---------------------------------------------------------
__global__ void lat_init_kernel(const float* __restrict__ lats)
{
    int i = blockIdx.x * 256 + threadIdx.x;
    g_lat[i] = lats[i & (NQ * DIM - 1)];
}

// ---------------- host wrappers ---------------------------------------------------------
static float* s_part = nullptr;

static void gemm_raw(const bf16* A, const bf16* Bt, const float* bias, float* C,
                     int M, int N, int K, int S, int act, int accum)
{
    int nc = 3 * (K >> 6);
    dim3 grid(N / 128, (M + 127) / 128, S);
    gemm_mma<<<grid, 256, GEMM_SMEM>>>(A, Bt, (S == 1) ? bias : nullptr, C, s_part,
                                       M, N, K, nc / S, act, accum);
}

static void gemm(const bf16* A, const bf16* Bt, const float* bias, float* C, bf16* outs,
                 int M, int N, int K, int S, int act, int accum)
{
    gemm_raw(A, Bt, bias, C, M, N, K, S, act, accum);
    if (S > 1) {
        int MN4 = M * N / 4;
        reduce_ep4<<<(MN4 + 255) / 256, 256>>>(s_part, bias, C, outs, MN4, N, S, act, accum);
    }
}

extern "C" void kernel_launch(void* const* d_in, const int* in_sizes, int n_in,
                              void* d_out, int out_size)
{
    const float* x          = (const float*)d_in[0];
    const int*   ts         = (const int*)  d_in[1];
    const float* latents    = (const float*)d_in[2];
    const float* proj_in_w  = (const float*)d_in[3];
    const float* proj_in_b  = (const float*)d_in[4];
    const float* time1_w    = (const float*)d_in[5];
    const float* time1_b    = (const float*)d_in[6];
    const float* time2_w    = (const float*)d_in[7];
    const float* time2_b    = (const float*)d_in[8];
    const float* n1_g       = (const float*)d_in[9];
    const float* n1_b       = (const float*)d_in[10];
    const float* n2_g       = (const float*)d_in[11];
    const float* n2_b       = (const float*)d_in[12];
    const float* wq         = (const float*)d_in[13];
    const float* wkv        = (const float*)d_in[14];
    const float* wo         = (const float*)d_in[15];
    const float* ff_g       = (const float*)d_in[16];
    const float* ff_b       = (const float*)d_in[17];
    const float* ff_w1      = (const float*)d_in[18];
    const float* ff_w2      = (const float*)d_in[19];
    const float* ada_w      = (const float*)d_in[20];
    const float* ada_b      = (const float*)d_in[21];
    const float* proj_out_w = (const float*)d_in[22];
    const float* proj_out_b = (const float*)d_in[23];
    const float* out_g      = (const float*)d_in[24];
    const float* out_b      = (const float*)d_in[25];

    float *p_h, *p_lat, *p_qkv, *p_ada8, *p_obuf, *p_part;
    bf16 *p_xs, *p_hns, *p_latms, *p_attns, *p_ffs, *p_lats, *p_stembs, *p_psp, *p_wspl, *p_hnT;
    bf16 *pw_pi, *pw_po, *pw_qkvl, *pw_o, *pw_ada, *pw_f1, *pw_f2;
    cudaGetSymbolAddress((void**)&p_h,      g_h);
    cudaGetSymbolAddress((void**)&p_lat,    g_lat);
    cudaGetSymbolAddress((void**)&p_qkv,    g_qkv);
    cudaGetSymbolAddress((void**)&p_ada8,   g_ada8);
    cudaGetSymbolAddress((void**)&p_obuf,   g_obuf);
    cudaGetSymbolAddress((void**)&p_part,   g_part);
    cudaGetSymbolAddress((void**)&p_xs,     g_xs);
    cudaGetSymbolAddress((void**)&p_hns,    g_hns);
    cudaGetSymbolAddress((void**)&p_latms,  g_latms);
    cudaGetSymbolAddress((void**)&p_attns,  g_attns);
    cudaGetSymbolAddress((void**)&p_ffs,    g_ffs);
    cudaGetSymbolAddress((void**)&p_lats,   g_lats);
    cudaGetSymbolAddress((void**)&p_stembs, g_stembs);
    cudaGetSymbolAddress((void**)&p_psp,    g_psp);
    cudaGetSymbolAddress((void**)&p_wspl,   g_wspl);
    cudaGetSymbolAddress((void**)&p_hnT,    g_hnT);
    cudaGetSymbolAddress((void**)&pw_pi,    w_pi);
    cudaGetSymbolAddress((void**)&pw_po,    w_po);
    cudaGetSymbolAddress((void**)&pw_qkvl,  w_qkvl);
    cudaGetSymbolAddress((void**)&pw_o,     w_o);
    cudaGetSymbolAddress((void**)&pw_ada,   w_ada);
    cudaGetSymbolAddress((void**)&pw_f1,    w_f1);
    cudaGetSymbolAddress((void**)&pw_f2,    w_f2);
    s_part = p_part;

    cudaFuncSetAttribute(gemm_mma, cudaFuncAttributeMaxDynamicSharedMemorySize, GEMM_SMEM);
    cudaFuncSetAttribute(gemm_bat, cudaFuncAttributeMaxDynamicSharedMemorySize, GEMM_SMEM);
    cudaFuncSetAttribute(gemm_s32, cudaFuncAttributeMaxDynamicSharedMemorySize, S32_SMEM);

    // forked stream + events (created once; identical captured work every call)
    static cudaStream_t s2 = nullptr;
    static cudaEvent_t evF = nullptr, evA = nullptr, evQ = nullptr, evR = nullptr;
    if (s2 == nullptr) {
        cudaStreamCreateWithFlags(&s2, cudaStreamNonBlocking);
        cudaEventCreateWithFlags(&evF, cudaEventDisableTiming);
        cudaEventCreateWithFlags(&evA, cudaEventDisableTiming);
        cudaEventCreateWithFlags(&evQ, cudaEventDisableTiming);
        cudaEventCreateWithFlags(&evR, cudaEventDisableTiming);
    }

    // ---- prologue (main stream): pieces the x-path needs ----------------------
    time_mlp_kernel<<<BATCH, 1024>>>(ts, time1_w, time1_b, time2_w, time2_b);
    lat_init_kernel<<<(ML * DIM) / 256, 256>>>(latents);
    wsplit_t<<<dim3(32, 12, 1), 256>>>(proj_in_w, pw_pi, 768, 1024, 0, 0);
    convert_a<<<(int)(((size_t)MX * 768) / 1024), 256>>>(x, p_xs, 768);

    // ---- fork: weight conversions on s2, ordered by first consumption ---------
    cudaEventRecord(evF, 0);
    cudaStreamWaitEvent(s2, evF, 0);
    wsplit_t<<<dim3(128, 16, 8), 256, 0, s2>>>(ada_w, pw_ada, 1024, 4096, (size_t)1024*4096, (size_t)4096*2048);
    cudaEventRecord(evA, s2);
    wsplit_t<<<dim3(32, 16, 8),  256, 0, s2>>>(wq,  pw_qkvl,                     1024, 1024, (size_t)1024*1024, (size_t)3072*2048);
    wsplit_t<<<dim3(64, 16, 8),  256, 0, s2>>>(wkv, pw_qkvl + (size_t)1024*2048, 1024, 2048, (size_t)1024*2048, (size_t)3072*2048);
    cudaEventRecord(evQ, s2);
    wsplit_t<<<dim3(32, 16, 8),  256, 0, s2>>>(wo,    pw_o,   1024, 1024, (size_t)1024*1024, (size_t)1024*2048);
    wsplit_t<<<dim3(128, 16, 8), 256, 0, s2>>>(ff_w1, pw_f1,  1024, 4096, (size_t)1024*4096, (size_t)4096*2048);
    wsplit_t<<<dim3(32, 64, 8),  256, 0, s2>>>(ff_w2, pw_f2,  4096, 1024, (size_t)4096*1024, (size_t)1024*8192);
    wsplit_t<<<dim3(32, 16, 1),  256, 0, s2>>>(proj_out_w, pw_po, 1024, 1024, 0, 0);
    cudaEventRecord(evR, s2);

    // ---- x-path on main stream (overlaps with s2 conversions) -----------------
    gemm_raw(p_xs, pw_pi, nullptr, p_h, MX, DIM, 768, 1, 0, 0);
    ln_h_kernel<<<MX, 256>>>(proj_in_b);
    hnt_kernel<<<dim3(NPAD / 32, 32, BATCH), 256>>>();

    // ---- join 1: ada weights ready -> ada GEMM --------------------------------
    cudaStreamWaitEvent(0, evA, 0);
    {
        gemm_s32<<<dim3((8 * 4096) / 128, 1, 4), 256, S32_SMEM>>>(
            p_stembs, pw_ada, s_part, 8 * 4096, DIM, 12);
        int MN4 = (BATCH * 8 * 4096) / 4;
        reduce_ep4<<<(MN4 + 255) / 256, 256>>>(s_part, ada_b, p_ada8, nullptr,
                                               MN4, 8 * 4096, 4, 0, 0);
    }

    // initial modulated LN for layer 0
    ln_mod_kernel<<<ML, 256>>>(p_lat, nullptr, p_latms, n2_g, n2_b,
                               p_ada8, ADALD, 0, DIM);

    // ---- join 2: qkv weights ready -> layer loop -------------------------------
    cudaStreamWaitEvent(0, evQ, 0);

    for (int i = 0; i < 8; i++) {
        const float* wkv_i = wkv + (size_t)i * 1024 * 2048;
        const float* n1g_i = n1_g + i * DIM;
        const float* n1b_i = n1_b + i * DIM;

        // fused q + latent kv: [256, 3072]
        gemm(p_latms, pw_qkvl + (size_t)i*3072*2048, nullptr, p_qkv, nullptr,
             ML, 3072, DIM, 6, 0, 0);

        pproj_kernel<<<BATCH * HEADS, 256>>>(wkv_i, n1g_i, n1b_i);

        // token scores (0..255): P' @ hn^T, segments -> 3 partial planes
        gemm_bat<<<dim3(2, 3, BATCH), 256, GEMM_SMEM>>>(
            p_psp, p_hns, p_part, 256, 1024, 256,
            (size_t)128*2048, (size_t)TOK*2048, (size_t)128*256, SEG_S);

        softmax_kernel<<<BATCH * HEADS, 256>>>();

        // U = W @ hn, segment-split (grid.y=3) -> 3 partial planes (oproj sums)
        gemm_bat<<<dim3(8, 3, BATCH), 256, GEMM_SMEM>>>(
            p_wspl, p_hnT, p_part, 1024, NPAD, 1024,
            (size_t)128*(2*NPAD), (size_t)1024*(2*NPAD), (size_t)128*1024, USEG);

        oproj_kernel<<<BATCH * HEADS, 256>>>(wkv_i, n1g_i, n1b_i);

        // join 3 (layer 0 only): wo/f1/f2/po weights ready
        if (i == 0) cudaStreamWaitEvent(0, evR, 0);

        // wo projection -> partials; fused reduce + residual + ff-LN -> latms
        gemm_raw(p_attns, pw_o + (size_t)i*1024*2048, nullptr, nullptr,
                 ML, DIM, DIM, 16, 0, 0);
        reduce_ln<<<ML, 256>>>(s_part, 16, p_lat, p_latms,
                               ff_g + i*DIM, ff_b + i*DIM,
                               p_ada8 + (size_t)i*4096, 2*DIM, 3*DIM);

        // FF
        gemm(p_latms, pw_f1 + (size_t)i*4096*2048, nullptr, nullptr, p_ffs,
             ML, FFI, DIM, 8, 1, 0);
        gemm_raw(p_ffs, pw_f2 + (size_t)i*1024*8192, nullptr, nullptr,
                 ML, DIM, FFI, 16, 0, 0);
        if (i < 7)
            reduce_ln<<<ML, 256>>>(s_part, 16, p_lat, p_latms,
                                   n2_g + (i+1)*DIM, n2_b + (i+1)*DIM,
                                   p_ada8 + (size_t)(i+1)*4096, 0, DIM);
        else
            reduce_ln<<<ML, 256>>>(s_part, 16, p_lat, p_lats,
                                   nullptr, nullptr, nullptr, 0, 0);
    }

    gemm(p_lats, pw_po, proj_out_b, p_obuf, nullptr, ML, DIM, DIM, 16, 0, 0);
    ln_mod_kernel<<<ML, 256>>>(p_obuf, (float*)d_out, nullptr, out_g, out_b,
                               nullptr, 0, 0, 0);
}

// round 17
// speedup vs baseline: 1.0141x; 1.0141x over previous
#include <cuda_runtime.h>
#include <cuda_bf16.h>
#include <math.h>
#include <cstdint>
#include <cstddef>

#define BATCH 32
#define TOK 257
#define NQ 8
#define DIM 1024
#define MX (BATCH*TOK)      /* 8224 */
#define ML (BATCH*NQ)       /* 256  */
#define HEADS 16
#define DHEAD 64
#define FFI 4096
#define EPS 1e-5f
#define NPAD 256            /* token dim for scores/U gemm (token 256 analytic) */
#define ADALD (8*4096)
#define SEG_S ((size_t)32*128*256)    /* scores partial plane stride */

typedef __nv_bfloat16 bf16;

// ---------------- scratch (device globals) ----------------------------------
__device__ float g_temb[BATCH*DIM];
__device__ float g_h[MX*DIM];
__device__ float g_lat[ML*DIM];
__device__ float g_qkv[ML*3072];
__device__ float g_ada8[BATCH*8*4096];
__device__ float g_obuf[ML*DIM];
__device__ float g_part[8*1024*1024];
__device__ float g_rowc[BATCH*128];
__device__ float g_s256[BATCH*128];
__device__ float g_w256[BATCH*128];
__device__ float g_swsum[BATCH*128];
__device__ float g_uu[BATCH*128*1024];
__device__ float g_olat[BATCH*128*64];

// split bf16 buffers: [m][2K] = [hi(K) | lo(K)]
__device__ bf16 g_xs   [(size_t)MX*1536];
__device__ bf16 g_hns  [(size_t)MX*2048];
__device__ bf16 g_latms[ML*2048];
__device__ bf16 g_attns[ML*2048];
__device__ bf16 g_ffs  [ML*8192];
__device__ bf16 g_lats [ML*2048];
__device__ bf16 g_stembs[BATCH*2048];
__device__ bf16 g_psp  [(size_t)BATCH*128*2048];
__device__ bf16 g_wspl [(size_t)BATCH*128*(2*NPAD)];
__device__ bf16 g_hnT  [(size_t)BATCH*1024*(2*NPAD)];

// split bf16 transposed weights: [N][2K]
__device__ bf16 w_pi  [(size_t)1024*1536];
__device__ bf16 w_po  [(size_t)1024*2048];
__device__ bf16 w_qkvl[(size_t)8*3072*2048];
__device__ bf16 w_o   [(size_t)8*1024*2048];
__device__ bf16 w_ada [(size_t)8*4096*2048];
__device__ bf16 w_f1  [(size_t)8*4096*2048];
__device__ bf16 w_f2  [(size_t)8*1024*8192];

// ---------------- helpers ------------------------------------------------------
__device__ __forceinline__ float siluf(float x){ return x / (1.f + expf(-x)); }
__device__ __forceinline__ float geluf(float x){ return 0.5f * x * (1.f + erff(x * 0.70710678118654752f)); }

__device__ __forceinline__ uint32_t smem_u32(const void* p){
    uint32_t a;
    asm("{ .reg .u64 t; cvta.to.shared.u64 t, %1; cvt.u32.u64 %0, t; }" : "=r"(a) : "l"(p));
    return a;
}
#define SWZ(x) ((x) ^ (((x) >> 3) & 0x70))

__device__ __forceinline__ void ldsm4(uint32_t& r0, uint32_t& r1, uint32_t& r2, uint32_t& r3, uint32_t a){
    asm volatile("ldmatrix.sync.aligned.m8n8.x4.shared.b16 {%0,%1,%2,%3}, [%4];"
                 : "=r"(r0),"=r"(r1),"=r"(r2),"=r"(r3) : "r"(a));
}
__device__ __forceinline__ void mma16816(float* c, const uint32_t* a, uint32_t b0, uint32_t b1){
    asm volatile("mma.sync.aligned.m16n8k16.row.col.f32.bf16.bf16.f32 "
                 "{%0,%1,%2,%3}, {%4,%5,%6,%7}, {%8,%9}, {%0,%1,%2,%3};"
                 : "+f"(c[0]),"+f"(c[1]),"+f"(c[2]),"+f"(c[3])
                 : "r"(a[0]),"r"(a[1]),"r"(a[2]),"r"(a[3]), "r"(b0),"r"(b1));
}

#define ASTG (128*128)
#define BSTG (128*128)
#define STG  (ASTG+BSTG)
#define GEMM_SMEM (3*STG)       /* 96 KB, 3-stage -> 2 CTAs/SM */

// small-M kernel: 32x128 tile
#define ASTG2 (32*128)
#define BSTG2 (128*128)
#define STG2  (ASTG2+BSTG2)
#define S32_SMEM (3*STG2)       /* 60 KB, 3-stage -> 3 CTAs/SM */

// ======================= split-3 bf16 GEMM (128x128, split-K) ==================
__global__ void __launch_bounds__(256, 2) gemm_mma(
    const bf16* __restrict__ A, const bf16* __restrict__ Bt,
    const float* __restrict__ bias, float* __restrict__ C,
    float* __restrict__ part,
    int M, int N, int K, int cz, int act, int accum)
{
    extern __shared__ __align__(1024) char smem[];
    const uint32_t sb = smem_u32(smem);
    const int tid = threadIdx.x;
    const int wid = tid >> 5, lane = tid & 31;
    const int wm = wid & 3, wn = wid >> 2;

    const int m_base = blockIdx.y * 128;
    const int n_base = blockIdx.x * 128;
    const int cps = K >> 6;
    const int cbeg = blockIdx.z * cz;
    const size_t rstride = 2 * (size_t)K;

    const int ldrow = tid >> 3;
    const int ldc16 = tid & 7;

    auto load_chunk = [&](int t, int slot){
        int c = cbeg + t;
        if (t < cz) {
            int seg = c / cps, w = c - seg * cps;
            int aoff = ((seg == 2) ? K : 0) + w * 64;
            int boff = ((seg == 1) ? K : 0) + w * 64;
            uint32_t ab = sb + (uint32_t)slot * STG;
            uint32_t bb = ab + ASTG;
            #pragma unroll
            for (int i = 0; i < 4; i++) {
                int row = ldrow + i * 32;
                int gm = m_base + row;
                int sz = (gm < M) ? 16 : 0;
                if (gm >= M) gm = 0;
                const bf16* srcA = A + (size_t)gm * rstride + aoff + ldc16 * 8;
                asm volatile("cp.async.cg.shared.global [%0], [%1], 16, %2;"
                             :: "r"(ab + SWZ(row * 128 + ldc16 * 16)), "l"(srcA), "r"(sz));
                const bf16* srcB = Bt + (size_t)(n_base + row) * rstride + boff + ldc16 * 8;
                asm volatile("cp.async.cg.shared.global [%0], [%1], 16;"
                             :: "r"(bb + SWZ(row * 128 + ldc16 * 16)), "l"(srcB));
            }
        }
        asm volatile("cp.async.commit_group;" ::: "memory");
    };

    float acc[2][8][4];
    #pragma unroll
    for (int i = 0; i < 2; i++)
        #pragma unroll
        for (int j = 0; j < 8; j++)
            #pragma unroll
            for (int k = 0; k < 4; k++) acc[i][j][k] = 0.f;

    const int lrow = lane & 15;
    const int lhi  = (lane >> 4) & 1;
    uint32_t a_ro[2], a_rx[2], b_ro[4], b_rx[4];
    #pragma unroll
    for (int f = 0; f < 2; f++) {
        int r = wm * 32 + f * 16 + lrow;
        a_ro[f] = r * 128; a_rx[f] = ((r & 7) << 4);
    }
    #pragma unroll
    for (int g = 0; g < 4; g++) {
        int r = wn * 64 + g * 16 + lrow;
        b_ro[g] = r * 128; b_rx[g] = ((r & 7) << 4);
    }
    const uint32_t cb0 = lhi * 16;

    load_chunk(0, 0); load_chunk(1, 1);
    int sl = 0;

    for (int t = 0; t < cz; t++) {
        asm volatile("cp.async.wait_group 1;" ::: "memory");
        __syncthreads();
        int nsl = sl + 2; if (nsl >= 3) nsl -= 3;
        load_chunk(t + 2, nsl);
        uint32_t ab = sb + (uint32_t)sl * STG;
        uint32_t bb = ab + ASTG;
        #pragma unroll
        for (int ks = 0; ks < 4; ks++) {
            uint32_t cbyte = cb0 + ks * 32;
            uint32_t ra[2][4], rb[4][4];
            #pragma unroll
            for (int f = 0; f < 2; f++)
                ldsm4(ra[f][0], ra[f][1], ra[f][2], ra[f][3], ab + a_ro[f] + (cbyte ^ a_rx[f]));
            #pragma unroll
            for (int g = 0; g < 4; g++)
                ldsm4(rb[g][0], rb[g][1], rb[g][2], rb[g][3], bb + b_ro[g] + (cbyte ^ b_rx[g]));
            #pragma unroll
            for (int mt = 0; mt < 2; mt++)
                #pragma unroll
                for (int g = 0; g < 4; g++) {
                    mma16816(acc[mt][2*g],   ra[mt], rb[g][0], rb[g][2]);
                    mma16816(acc[mt][2*g+1], ra[mt], rb[g][1], rb[g][3]);
                }
        }
        sl = (sl + 1 == 3) ? 0 : sl + 1;
    }

    const int g4 = lane >> 2, t4 = lane & 3;
    const bool direct = (gridDim.z == 1);
    #pragma unroll
    for (int mt = 0; mt < 2; mt++) {
        #pragma unroll
        for (int r2 = 0; r2 < 2; r2++) {
            int gm = m_base + wm * 32 + mt * 16 + r2 * 8 + g4;
            if (gm >= M) continue;
            #pragma unroll
            for (int nt = 0; nt < 8; nt++) {
                int gn = n_base + wn * 64 + nt * 8 + t4 * 2;
                float v0 = acc[mt][nt][r2 * 2 + 0];
                float v1 = acc[mt][nt][r2 * 2 + 1];
                if (direct) {
                    if (bias) { v0 += bias[gn]; v1 += bias[gn + 1]; }
                    if (act)  { v0 = geluf(v0); v1 = geluf(v1); }
                    float* cp = C + (size_t)gm * N + gn;
                    if (accum) { cp[0] += v0; cp[1] += v1; }
                    else       { *reinterpret_cast<float2*>(cp) = make_float2(v0, v1); }
                } else {
                    float* pp = part + ((size_t)blockIdx.z * M + gm) * N + gn;
                    *reinterpret_cast<float2*>(pp) = make_float2(v0, v1);
                }
            }
        }
    }
}

// ============ small-M split-3 GEMM: 32x128 tile, partials only =================
__global__ void __launch_bounds__(256, 3) gemm_s32(
    const bf16* __restrict__ A, const bf16* __restrict__ Bt,
    float* __restrict__ part, int N, int K, int cz)
{
    extern __shared__ __align__(1024) char smem[];
    const uint32_t sb = smem_u32(smem);
    const int tid = threadIdx.x;
    const int wid = tid >> 5, lane = tid & 31;
    const int wn = wid;

    const int n_base = blockIdx.x * 128;
    const int cps = K >> 6;
    const int cbeg = blockIdx.z * cz;
    const size_t rstride = 2 * (size_t)K;

    const int ldrow = tid >> 3;
    const int ldc16 = tid & 7;

    auto load_chunk = [&](int t, int slot){
        int c = cbeg + t;
        if (t < cz) {
            int seg = c / cps, w = c - seg * cps;
            int aoff = ((seg == 2) ? K : 0) + w * 64;
            int boff = ((seg == 1) ? K : 0) + w * 64;
            uint32_t ab = sb + (uint32_t)slot * STG2;
            uint32_t bb = ab + ASTG2;
            {
                const bf16* srcA = A + (size_t)(ldrow & 31) * rstride + aoff + ldc16 * 8;
                if (ldrow < 32)
                    asm volatile("cp.async.cg.shared.global [%0], [%1], 16;"
                                 :: "r"(ab + SWZ(ldrow * 128 + ldc16 * 16)), "l"(srcA));
            }
            #pragma unroll
            for (int i = 0; i < 4; i++) {
                int row = ldrow + i * 32;
                const bf16* srcB = Bt + (size_t)(n_base + row) * rstride + boff + ldc16 * 8;
                asm volatile("cp.async.cg.shared.global [%0], [%1], 16;"
                             :: "r"(bb + SWZ(row * 128 + ldc16 * 16)), "l"(srcB));
            }
        }
        asm volatile("cp.async.commit_group;" ::: "memory");
    };

    float acc[2][2][4];
    #pragma unroll
    for (int i = 0; i < 2; i++)
        #pragma unroll
        for (int j = 0; j < 2; j++)
            #pragma unroll
            for (int k = 0; k < 4; k++) acc[i][j][k] = 0.f;

    const int lrow = lane & 15;
    const int lhi  = (lane >> 4) & 1;
    uint32_t a_ro[2], a_rx[2], b_ro, b_rx;
    #pragma unroll
    for (int f = 0; f < 2; f++) {
        int r = f * 16 + lrow;
        a_ro[f] = r * 128; a_rx[f] = ((r & 7) << 4);
    }
    {
        int r = wn * 16 + lrow;
        b_ro = r * 128; b_rx = ((r & 7) << 4);
    }
    const uint32_t cb0 = lhi * 16;

    load_chunk(0, 0); load_chunk(1, 1);
    int sl = 0;

    for (int t = 0; t < cz; t++) {
        asm volatile("cp.async.wait_group 1;" ::: "memory");
        __syncthreads();
        int nsl = sl + 2; if (nsl >= 3) nsl -= 3;
        load_chunk(t + 2, nsl);
        uint32_t ab = sb + (uint32_t)sl * STG2;
        uint32_t bb = ab + ASTG2;
        #pragma unroll
        for (int ks = 0; ks < 4; ks++) {
            uint32_t cbyte = cb0 + ks * 32;
            uint32_t ra[2][4], rb[4];
            #pragma unroll
            for (int f = 0; f < 2; f++)
                ldsm4(ra[f][0], ra[f][1], ra[f][2], ra[f][3], ab + a_ro[f] + (cbyte ^ a_rx[f]));
            ldsm4(rb[0], rb[1], rb[2], rb[3], bb + b_ro + (cbyte ^ b_rx));
            #pragma unroll
            for (int mt = 0; mt < 2; mt++) {
                mma16816(acc[mt][0], ra[mt], rb[0], rb[2]);
                mma16816(acc[mt][1], ra[mt], rb[1], rb[3]);
            }
        }
        sl = (sl + 1 == 3) ? 0 : sl + 1;
    }

    const int g4 = lane >> 2, t4 = lane & 3;
    #pragma unroll
    for (int mt = 0; mt < 2; mt++) {
        #pragma unroll
        for (int r2 = 0; r2 < 2; r2++) {
            int gm = mt * 16 + r2 * 8 + g4;
            #pragma unroll
            for (int nt = 0; nt < 2; nt++) {
                int gn = n_base + wn * 16 + nt * 8 + t4 * 2;
                float v0 = acc[mt][nt][r2 * 2 + 0];
                float v1 = acc[mt][nt][r2 * 2 + 1];
                float* pp = part + ((size_t)blockIdx.z * 32 + gm) * N + gn;
                *reinterpret_cast<float2*>(pp) = make_float2(v0, v1);
            }
        }
    }
}

// ============ batched split-3 GEMM (blockIdx.z = batch) ========================
__global__ void __launch_bounds__(256, 2) gemm_bat(
    const bf16* __restrict__ A, const bf16* __restrict__ Bt, float* __restrict__ C,
    int N, int K, int ldc, size_t sA, size_t sB, size_t sC, size_t sSeg)
{
    extern __shared__ __align__(1024) char smem[];
    const uint32_t sb = smem_u32(smem);
    const int tid = threadIdx.x;
    const int wid = tid >> 5, lane = tid & 31;
    const int wm = wid & 3, wn = wid >> 2;
    const int bat = blockIdx.z;
    A  += (size_t)bat * sA;
    Bt += (size_t)bat * sB;
    C  += (size_t)bat * sC + (size_t)blockIdx.y * sSeg;

    const int n_base = blockIdx.x * 128;
    const int cps = K >> 6;
    const int cbeg = (gridDim.y > 1) ? (int)blockIdx.y * cps : 0;
    const int cz   = (gridDim.y > 1) ? cps : 3 * cps;
    const size_t rstride = 2 * (size_t)K;

    const int ldrow = tid >> 3;
    const int ldc16 = tid & 7;

    auto load_chunk = [&](int t, int slot){
        if (t < cz) {
            int c = cbeg + t;
            int seg = c / cps, w = c - seg * cps;
            int aoff = ((seg == 2) ? K : 0) + w * 64;
            int boff = ((seg == 1) ? K : 0) + w * 64;
            uint32_t ab = sb + (uint32_t)slot * STG;
            uint32_t bb = ab + ASTG;
            #pragma unroll
            for (int i = 0; i < 4; i++) {
                int row = ldrow + i * 32;
                const bf16* srcA = A + (size_t)row * rstride + aoff + ldc16 * 8;
                asm volatile("cp.async.cg.shared.global [%0], [%1], 16;"
                             :: "r"(ab + SWZ(row * 128 + ldc16 * 16)), "l"(srcA));
                const bf16* srcB = Bt + (size_t)(n_base + row) * rstride + boff + ldc16 * 8;
                asm volatile("cp.async.cg.shared.global [%0], [%1], 16;"
                             :: "r"(bb + SWZ(row * 128 + ldc16 * 16)), "l"(srcB));
            }
        }
        asm volatile("cp.async.commit_group;" ::: "memory");
    };

    float acc[2][8][4];
    #pragma unroll
    for (int i = 0; i < 2; i++)
        #pragma unroll
        for (int j = 0; j < 8; j++)
            #pragma unroll
            for (int k = 0; k < 4; k++) acc[i][j][k] = 0.f;

    const int lrow = lane & 15;
    const int lhi  = (lane >> 4) & 1;
    uint32_t a_ro[2], a_rx[2], b_ro[4], b_rx[4];
    #pragma unroll
    for (int f = 0; f < 2; f++) {
        int r = wm * 32 + f * 16 + lrow;
        a_ro[f] = r * 128; a_rx[f] = ((r & 7) << 4);
    }
    #pragma unroll
    for (int g = 0; g < 4; g++) {
        int r = wn * 64 + g * 16 + lrow;
        b_ro[g] = r * 128; b_rx[g] = ((r & 7) << 4);
    }
    const uint32_t cb0 = lhi * 16;

    load_chunk(0, 0); load_chunk(1, 1);
    int sl = 0;

    for (int t = 0; t < cz; t++) {
        asm volatile("cp.async.wait_group 1;" ::: "memory");
        __syncthreads();
        int nsl = sl + 2; if (nsl >= 3) nsl -= 3;
        load_chunk(t + 2, nsl);
        uint32_t ab = sb + (uint32_t)sl * STG;
        uint32_t bb = ab + ASTG;
        #pragma unroll
        for (int ks = 0; ks < 4; ks++) {
            uint32_t cbyte = cb0 + ks * 32;
            uint32_t ra[2][4], rb[4][4];
            #pragma unroll
            for (int f = 0; f < 2; f++)
                ldsm4(ra[f][0], ra[f][1], ra[f][2], ra[f][3], ab + a_ro[f] + (cbyte ^ a_rx[f]));
            #pragma unroll
            for (int g = 0; g < 4; g++)
                ldsm4(rb[g][0], rb[g][1], rb[g][2], rb[g][3], bb + b_ro[g] + (cbyte ^ b_rx[g]));
            #pragma unroll
            for (int mt = 0; mt < 2; mt++)
                #pragma unroll
                for (int g = 0; g < 4; g++) {
                    mma16816(acc[mt][2*g],   ra[mt], rb[g][0], rb[g][2]);
                    mma16816(acc[mt][2*g+1], ra[mt], rb[g][1], rb[g][3]);
                }
        }
        sl = (sl + 1 == 3) ? 0 : sl + 1;
    }

    const int g4 = lane >> 2, t4 = lane & 3;
    #pragma unroll
    for (int mt = 0; mt < 2; mt++) {
        #pragma unroll
        for (int r2 = 0; r2 < 2; r2++) {
            int gm = wm * 32 + mt * 16 + r2 * 8 + g4;
            #pragma unroll
            for (int nt = 0; nt < 8; nt++) {
                int gn = n_base + wn * 64 + nt * 8 + t4 * 2;
                float v0 = acc[mt][nt][r2 * 2 + 0];
                float v1 = acc[mt][nt][r2 * 2 + 1];
                *reinterpret_cast<float2*>(C + (size_t)gm * ldc + gn) = make_float2(v0, v1);
            }
        }
    }
}

// ---------------- split-K reduce + epilogue (float4) ---------------------------
__global__ void reduce_ep4(const float* __restrict__ part, const float* __restrict__ bias,
                           float* __restrict__ C, bf16* __restrict__ outs,
                           int MN4, int N, int S, int act, int accum)
{
    int i4 = blockIdx.x * 256 + threadIdx.x;
    if (i4 >= MN4) return;
    size_t base = (size_t)i4 * 4;
    int m = (int)(base / N), n = (int)(base % N);
    float4 s = make_float4(0.f, 0.f, 0.f, 0.f);
    for (int t = 0; t < S; t++) {
        float4 p = reinterpret_cast<const float4*>(part)[(size_t)t * MN4 + i4];
        s.x += p.x; s.y += p.y; s.z += p.z; s.w += p.w;
    }
    if (bias) {
        float4 bb = reinterpret_cast<const float4*>(bias)[n >> 2];
        s.x += bb.x; s.y += bb.y; s.z += bb.z; s.w += bb.w;
    }
    if (act) { s.x = geluf(s.x); s.y = geluf(s.y); s.z = geluf(s.z); s.w = geluf(s.w); }
    if (C) {
        if (accum) {
            float4 c = reinterpret_cast<float4*>(C)[i4];
            s.x += c.x; s.y += c.y; s.z += c.z; s.w += c.w;
        }
        reinterpret_cast<float4*>(C)[i4] = s;
    }
    if (outs) {
        float y[4] = {s.x, s.y, s.z, s.w};
        union { bf16 b[4]; uint2 u; } hi, lo;
        #pragma unroll
        for (int j = 0; j < 4; j++) {
            bf16 h = __float2bfloat16(y[j]);
            hi.b[j] = h; lo.b[j] = __float2bfloat16(y[j] - __bfloat162float(h));
        }
        *reinterpret_cast<uint2*>(outs + (size_t)m * 2 * N + n)     = hi.u;
        *reinterpret_cast<uint2*>(outs + (size_t)m * 2 * N + N + n) = lo.u;
    }
}

// ---------------- block reduction helper ----------------------------------------
__device__ __forceinline__ void block_reduce2(float& s1, float& s2,
                                              float* sh1, float* sh2, int tid)
{
    #pragma unroll
    for (int o = 16; o > 0; o >>= 1) {
        s1 += __shfl_xor_sync(0xffffffffu, s1, o);
        s2 += __shfl_xor_sync(0xffffffffu, s2, o);
    }
    int w = tid >> 5, lane = tid & 31;
    if (lane == 0) { sh1[w] = s1; sh2[w] = s2; }
    __syncthreads();
    if (tid < 32) {
        float a = (tid < 8) ? sh1[tid] : 0.f;
        float c = (tid < 8) ? sh2[tid] : 0.f;
        #pragma unroll
        for (int o = 4; o > 0; o >>= 1) {
            a += __shfl_xor_sync(0xffffffffu, a, o);
            c += __shfl_xor_sync(0xffffffffu, c, o);
        }
        if (tid == 0) { sh1[0] = a; sh2[0] = c; }
    }
    __syncthreads();
    s1 = sh1[0]; s2 = sh2[0];
}

// ------ fused: split-K reduce + residual into lat + LN(+adaLN) -> split bf16 ----
__global__ void reduce_ln(const float* __restrict__ part, int S,
                          float* __restrict__ lat, bf16* __restrict__ outs,
                          const float* __restrict__ gamma, const float* __restrict__ beta,
                          const float* __restrict__ adap, int shift_off, int scale_off)
{
    int r = blockIdx.x, b = r >> 3, tid = threadIdx.x;
    __shared__ float sh1[8], sh2[8];
    const size_t MN4 = (size_t)ML * 256;
    size_t i4 = (size_t)r * 256 + tid;
    float4 v = reinterpret_cast<float4*>(lat)[i4];
    for (int t = 0; t < S; t++) {
        float4 p = reinterpret_cast<const float4*>(part)[(size_t)t * MN4 + i4];
        v.x += p.x; v.y += p.y; v.z += p.z; v.w += p.w;
    }
    reinterpret_cast<float4*>(lat)[i4] = v;
    float y[4] = {v.x, v.y, v.z, v.w};
    if (gamma) {
        float s1 = v.x + v.y + v.z + v.w;
        float s2 = v.x*v.x + v.y*v.y + v.z*v.z + v.w*v.w;
        block_reduce2(s1, s2, sh1, sh2, tid);
        float mean = s1 * (1.f / DIM);
        float var  = s2 * (1.f / DIM) - mean * mean;
        float inv  = rsqrtf(var + EPS);
        float4 g  = reinterpret_cast<const float4*>(gamma)[tid];
        float4 be = reinterpret_cast<const float4*>(beta)[tid];
        float4 sc = reinterpret_cast<const float4*>(adap + (size_t)b * ADALD + scale_off)[tid];
        float4 sf = reinterpret_cast<const float4*>(adap + (size_t)b * ADALD + shift_off)[tid];
        float gg[4]  = {g.x, g.y, g.z, g.w};
        float bb[4]  = {be.x, be.y, be.z, be.w};
        float scc[4] = {sc.x, sc.y, sc.z, sc.w};
        float sff[4] = {sf.x, sf.y, sf.z, sf.w};
        #pragma unroll
        for (int j = 0; j < 4; j++)
            y[j] = ((y[j] - mean) * inv * gg[j] + bb[j]) * (1.f + scc[j]) + sff[j];
    }
    union { bf16 b4[4]; uint2 u; } hi, lo;
    #pragma unroll
    for (int j = 0; j < 4; j++) {
        bf16 h = __float2bfloat16(y[j]);
        hi.b4[j] = h; lo.b4[j] = __float2bfloat16(y[j] - __bfloat162float(h));
    }
    int k0 = tid * 4;
    *reinterpret_cast<uint2*>(outs + (size_t)r * 2048 + k0)        = hi.u;
    *reinterpret_cast<uint2*>(outs + (size_t)r * 2048 + 1024 + k0) = lo.u;
}

// ---------------- conversions (vectorized) ---------------------------------------
__global__ void convert_a(const float* __restrict__ in, bf16* __restrict__ out, int K)
{
    size_t i4 = (size_t)blockIdx.x * 256 + threadIdx.x;
    size_t base = i4 * 4;
    int k = (int)(base % K);
    size_t m = base / K;
    float4 v = reinterpret_cast<const float4*>(in)[i4];
    float y[4] = {v.x, v.y, v.z, v.w};
    union { bf16 b[4]; uint2 u; } hi, lo;
    #pragma unroll
    for (int j = 0; j < 4; j++) {
        bf16 h = __float2bfloat16(y[j]);
        hi.b[j] = h; lo.b[j] = __float2bfloat16(y[j] - __bfloat162float(h));
    }
    *reinterpret_cast<uint2*>(out + m * 2 * K + k)     = hi.u;
    *reinterpret_cast<uint2*>(out + m * 2 * K + K + k) = lo.u;
}

// W [K][N] fp32 -> T [N][2K] split bf16; 64k x 32n tiles, 16B stores
__global__ void wsplit_t(const float* __restrict__ W, bf16* __restrict__ T,
                         int K, int N, size_t wStride, size_t tStride)
{
    __shared__ float tile[64][33];
    int l = blockIdx.z;
    W += (size_t)l * wStride;
    T += (size_t)l * tStride;
    int n0 = blockIdx.x * 32, k0 = blockIdx.y * 64;
    int c = threadIdx.x & 31, r0 = threadIdx.x >> 5;
    #pragma unroll
    for (int i = 0; i < 8; i++)
        tile[r0 + i * 8][c] = W[(size_t)(k0 + r0 + i * 8) * N + n0 + c];
    __syncthreads();
    int nn = threadIdx.x >> 3;
    int kg = (threadIdx.x & 7) * 8;
    union { bf16 b[8]; uint4 u; } hi, lo;
    #pragma unroll
    for (int j = 0; j < 8; j++) {
        float v = tile[kg + j][nn];
        bf16 h = __float2bfloat16(v);
        hi.b[j] = h; lo.b[j] = __float2bfloat16(v - __bfloat162float(h));
    }
    size_t n = n0 + nn;
    *reinterpret_cast<uint4*>(T + n * 2 * K + k0 + kg)     = hi.u;
    *reinterpret_cast<uint4*>(T + n * 2 * K + K + k0 + kg) = lo.u;
}

// ---------------- hn transpose (per batch): hnT[b][c][2*NPAD], tokens 0..255 ----
__global__ void hnt_kernel()
{
    __shared__ bf16 th[32][33], tl[32][33];
    int b = blockIdx.z;
    int n0 = blockIdx.x * 32;
    int c0 = blockIdx.y * 32;
    int tx = threadIdx.x & 31, ty = threadIdx.x >> 5;
    #pragma unroll
    for (int i = 0; i < 4; i++) {
        int n = n0 + ty + i * 8;
        const bf16* r = g_hns + ((size_t)(b * TOK + n)) * 2048;
        th[ty + i * 8][tx] = r[c0 + tx];
        tl[ty + i * 8][tx] = r[1024 + c0 + tx];
    }
    __syncthreads();
    #pragma unroll
    for (int i = 0; i < 4; i++) {
        int cc = c0 + ty + i * 8;
        int n = n0 + tx;
        bf16* o = g_hnT + ((size_t)b * 1024 + cc) * (2 * NPAD);
        o[n]        = th[tx][ty + i * 8];
        o[NPAD + n] = tl[tx][ty + i * 8];
    }
}

// ---------------- P projection (+ fused fp32 score for token 256) ----------------
__global__ void pproj_kernel(const float* __restrict__ wkv_i,
                             const float* __restrict__ n1g, const float* __restrict__ n1b)
{
    __shared__ float sq[8][64];
    __shared__ float swk[32][65];
    int bh = blockIdx.x; int b = bh >> 4, h = bh & 15;
    int tid = threadIdx.x;
    for (int i = tid; i < 512; i += 256) {
        int l = i >> 6, d = i & 63;
        sq[l][d] = g_qkv[((size_t)(b * 8 + l)) * 3072 + h * 64 + d] * 0.125f;
    }
    int lq = tid >> 5;
    int cl = tid & 31;
    float rcacc = 0.f, s256acc = 0.f;
    const bf16* h256 = g_hns + ((size_t)(b * TOK + 256)) * 2048;
    bf16* pr = g_psp + ((size_t)b * 128 + h * 8 + lq) * 2048;
    for (int c0 = 0; c0 < 1024; c0 += 32) {
        __syncthreads();
        for (int i = tid; i < 32 * 64; i += 256) {
            int cc = i >> 6, d = i & 63;
            swk[cc][d] = wkv_i[(size_t)(c0 + cc) * 2048 + h * 64 + d];
        }
        __syncthreads();
        float acc = 0.f;
        #pragma unroll 16
        for (int d = 0; d < 64; d++) acc += sq[lq][d] * swk[cl][d];
        int cc = c0 + cl;
        rcacc += acc * n1b[cc];
        float pg = acc * n1g[cc];
        float hv = __bfloat162float(h256[cc]) + __bfloat162float(h256[1024 + cc]);
        s256acc += pg * hv;
        bf16 hi = __float2bfloat16(pg);
        pr[cc] = hi;
        pr[1024 + cc] = __float2bfloat16(pg - __bfloat162float(hi));
    }
    #pragma unroll
    for (int o = 16; o; o >>= 1) {
        rcacc   += __shfl_xor_sync(0xffffffffu, rcacc, o);
        s256acc += __shfl_xor_sync(0xffffffffu, s256acc, o);
    }
    if (cl == 0) {
        g_rowc[b * 128 + h * 8 + lq] = rcacc;
        g_s256[b * 128 + h * 8 + lq] = s256acc;
    }
}

// -------- softmax: 256 gemm'd tokens + analytic token 256 + latent kv ------------
__global__ void softmax_kernel()
{
    int bh = blockIdx.x; int b = bh >> 4, h = bh & 15;
    int l = threadIdx.x >> 5, lane = threadIdx.x & 31;
    int row = h * 8 + l;
    const float* sc0 = g_part + ((size_t)b * 128 + row) * 256;
    const float* sc1 = sc0 + SEG_S;
    const float* sc2 = sc1 + SEG_S;
    float rc = g_rowc[b * 128 + row];
    float v[8];
    #pragma unroll
    for (int j = 0; j < 8; j++) {
        int n = lane + j * 32;
        v[j] = sc0[n] + sc1[n] + sc2[n] + rc;
    }
    float s256 = g_s256[b * 128 + row] + rc;
    float lv = -1e30f;
    if (lane < 8) {
        const float* qp = g_qkv + ((size_t)(b * 8 + l))    * 3072 + h * 64;
        const float* kp = g_qkv + ((size_t)(b * 8 + lane)) * 3072 + 1024 + h * 64;
        float s = 0.f;
        #pragma unroll 16
        for (int d = 0; d < 64; d++) s += qp[d] * kp[d];
        lv = s * 0.125f;
    }
    float m = fmaxf(s256, lv);
    #pragma unroll
    for (int j = 0; j < 8; j++) m = fmaxf(m, v[j]);
    #pragma unroll
    for (int o = 16; o; o >>= 1) m = fmaxf(m, __shfl_xor_sync(0xffffffffu, m, o));
    float sum8 = 0.f;
    #pragma unroll
    for (int j = 0; j < 8; j++) {
        v[j] = expf(v[j] - m);
        sum8 += v[j];
    }
    float e256 = expf(s256 - m);
    float le = (lane < 8) ? expf(lv - m) : 0.f;
    float both = sum8 + le;
    float toks = sum8;
    #pragma unroll
    for (int o = 16; o; o >>= 1) {
        both += __shfl_xor_sync(0xffffffffu, both, o);
        toks += __shfl_xor_sync(0xffffffffu, toks, o);
    }
    float inv = 1.f / (both + e256);
    if (lane == 0) {
        g_swsum[b * 128 + row] = (toks + e256) * inv;
        g_w256[b * 128 + row]  = e256 * inv;
    }

    bf16* wr = g_wspl + ((size_t)b * 128 + row) * (2 * NPAD);
    #pragma unroll
    for (int j = 0; j < 8; j++) {
        int n = lane + j * 32;
        float w = v[j] * inv;
        bf16 hi = __float2bfloat16(w);
        wr[n]        = hi;
        wr[NPAD + n] = __float2bfloat16(w - __bfloat162float(hi));
    }
    float myle = le * inv;
    float wl[8];
    #pragma unroll
    for (int n = 0; n < 8; n++) wl[n] = __shfl_sync(0xffffffffu, myle, n);
    const float* vb = g_qkv + ((size_t)(b * 8)) * 3072 + 2048 + h * 64;
    float a0 = 0.f, a1 = 0.f;
    #pragma unroll
    for (int n = 0; n < 8; n++) {
        const float* vp = vb + (size_t)n * 3072;
        a0 += wl[n] * vp[lane];
        a1 += wl[n] * vp[lane + 32];
    }
    float* op = g_olat + ((size_t)b * 128 + row) * 64;
    op[lane] = a0; op[lane + 32] = a1;
}

// ------- out projection: U from gemm + rank-1 token-256 update -------------------
__global__ void oproj_kernel(const float* __restrict__ wkv_i,
                             const float* __restrict__ n1g, const float* __restrict__ n1b)
{
    __shared__ float ut[8][1024];
    int bh = blockIdx.x; int b = bh >> 4, h = bh & 15;
    int tid = threadIdx.x;
    const bf16* h256 = g_hns + ((size_t)(b * TOK + 256)) * 2048;
    for (int i = tid; i < 8 * 1024; i += 256) {
        int l = i >> 10, c = i & 1023;
        int row = h * 8 + l;
        float hv = __bfloat162float(h256[c]) + __bfloat162float(h256[1024 + c]);
        float u = g_uu[((size_t)b * 128 + row) * 1024 + c] + g_w256[b * 128 + row] * hv;
        ut[l][c] = u * n1g[c] + g_swsum[b * 128 + row] * n1b[c];
    }
    __syncthreads();
    int l = tid >> 5, lane = tid & 31;
    int row = h * 8 + l;
    float a0 = g_olat[((size_t)b * 128 + row) * 64 + lane];
    float a1 = g_olat[((size_t)b * 128 + row) * 64 + lane + 32];
    const float* wv = wkv_i + 1024 + h * 64;
    #pragma unroll 4
    for (int c = 0; c < 1024; c++) {
        float u = ut[l][c];
        a0 += u * wv[(size_t)c * 2048 + lane];
        a1 += u * wv[(size_t)c * 2048 + lane + 32];
    }
    size_t m = (size_t)(b * 8 + l);
    bf16* ar = g_attns + m * 2048;
    int d0 = h * 64 + lane, d1 = d0 + 32;
    bf16 h0 = __float2bfloat16(a0);
    ar[d0] = h0; ar[1024 + d0] = __float2bfloat16(a0 - __bfloat162float(h0));
    bf16 h1 = __float2bfloat16(a1);
    ar[d1] = h1; ar[1024 + d1] = __float2bfloat16(a1 - __bfloat162float(h1));
}

// ---------------- timestep embedding + time MLP -------------------------------------
__global__ void time_mlp_kernel(const int* __restrict__ ts,
    const float* __restrict__ w1, const float* __restrict__ b1,
    const float* __restrict__ w2, const float* __restrict__ b2)
{
    __shared__ float s_emb[320];
    __shared__ float s_hid[1024];
    int b = blockIdx.x, t = threadIdx.x;
    if (t < 160) {
        double f   = exp(-9.210340371976184 * (double)t / 160.0);
        double arg = (double)ts[b] * f;
        s_emb[t]       = (float)cos(arg);
        s_emb[t + 160] = (float)sin(arg);
    }
    __syncthreads();
    float acc = b1[t];
    for (int k = 0; k < 320; k++) acc += s_emb[k] * w1[k * 1024 + t];
    s_hid[t] = siluf(acc);
    __syncthreads();
    float acc2 = b2[t];
    for (int k = 0; k < 1024; k++) acc2 += s_hid[k] * w2[k * 1024 + t];
    g_temb[b * 1024 + t] = acc2;
    float sv = siluf(acc2);
    bf16 h = __float2bfloat16(sv);
    g_stembs[b * 2048 + t]        = h;
    g_stembs[b * 2048 + 1024 + t] = __float2bfloat16(sv - __bfloat162float(h));
}

// ---------------- hn = LN(h + bias + temb) -> split bf16 ----------------------------
__global__ void ln_h_kernel(const float* __restrict__ pib)
{
    int r = blockIdx.x;
    int b = r / TOK;
    int tid = threadIdx.x;
    __shared__ float sh1[8], sh2[8];
    const float* hrow = g_h + (size_t)r * DIM;
    const float* trow = g_temb + b * DIM;
    float v[4]; float s1 = 0.f, s2 = 0.f;
    #pragma unroll
    for (int j = 0; j < 4; j++) {
        int k = tid + j * 256;
        float t = hrow[k] + pib[k] + trow[k];
        v[j] = t; s1 += t; s2 += t * t;
    }
    block_reduce2(s1, s2, sh1, sh2, tid);
    float mean = s1 * (1.f / DIM);
    float var  = s2 * (1.f / DIM) - mean * mean;
    float inv  = rsqrtf(var + EPS);
    bf16* out = g_hns + (size_t)r * 2048;
    #pragma unroll
    for (int j = 0; j < 4; j++) {
        int k = tid + j * 256;
        float y = (v[j] - mean) * inv;
        bf16 h = __float2bfloat16(y);
        out[k]        = h;
        out[1024 + k] = __float2bfloat16(y - __bfloat162float(h));
    }
}

// ---------------- LN (+adaLN) -> split bf16 / fp32 ----------------------------------
__global__ void ln_mod_kernel(const float* __restrict__ in,
    float* __restrict__ outf, bf16* __restrict__ outs,
    const float* __restrict__ gamma, const float* __restrict__ beta,
    const float* __restrict__ ada, int ada_ld, int shift_off, int scale_off)
{
    int r = blockIdx.x;
    int b = r >> 3;
    int tid = threadIdx.x;
    __shared__ float sh1[8], sh2[8];
    const float* row = in + (size_t)r * DIM;
    float v[4]; float s1 = 0.f, s2 = 0.f;
    #pragma unroll
    for (int j = 0; j < 4; j++) {
        int k = tid + j * 256;
        float t = row[k];
        v[j] = t; s1 += t; s2 += t * t;
    }
    block_reduce2(s1, s2, sh1, sh2, tid);
    float mean = s1 * (1.f / DIM);
    float var  = s2 * (1.f / DIM) - mean * mean;
    float inv  = rsqrtf(var + EPS);
    #pragma unroll
    for (int j = 0; j < 4; j++) {
        int k = tid + j * 256;
        float y = (v[j] - mean) * inv * gamma[k] + beta[k];
        if (ada) y = y * (1.f + ada[(size_t)b * ada_ld + scale_off + k])
                    + ada[(size_t)b * ada_ld + shift_off + k];
        if (outf) outf[(size_t)r * DIM + k] = y;
        if (outs) {
            bf16 h = __float2bfloat16(y);
            outs[(size_t)r * 2048 + k]        = h;
            outs[(size_t)r * 2048 + 1024 + k] = __float2bfloat16(y - __bfloat162float(h));
        }
    }
}

// ---------------- latent init ---------------------------------------------------------
__global__ void lat_init_kernel(const float* __restrict__ lats)
{
    int i = blockIdx.x * 256 + threadIdx.x;
    g_lat[i] = lats[i & (NQ * DIM - 1)];
}

// ---------------- host wrappers ---------------------------------------------------------
static float* s_part = nullptr;

static void gemm_raw(const bf16* A, const bf16* Bt, const float* bias, float* C,
                     int M, int N, int K, int S, int act, int accum)
{
    int nc = 3 * (K >> 6);
    dim3 grid(N / 128, (M + 127) / 128, S);
    gemm_mma<<<grid, 256, GEMM_SMEM>>>(A, Bt, (S == 1) ? bias : nullptr, C, s_part,
                                       M, N, K, nc / S, act, accum);
}

static void gemm(const bf16* A, const bf16* Bt, const float* bias, float* C, bf16* outs,
                 int M, int N, int K, int S, int act, int accum)
{
    gemm_raw(A, Bt, bias, C, M, N, K, S, act, accum);
    if (S > 1) {
        int MN4 = M * N / 4;
        reduce_ep4<<<(MN4 + 255) / 256, 256>>>(s_part, bias, C, outs, MN4, N, S, act, accum);
    }
}

extern "C" void kernel_launch(void* const* d_in, const int* in_sizes, int n_in,
                              void* d_out, int out_size)
{
    const float* x          = (const float*)d_in[0];
    const int*   ts         = (const int*)  d_in[1];
    const float* latents    = (const float*)d_in[2];
    const float* proj_in_w  = (const float*)d_in[3];
    const float* proj_in_b  = (const float*)d_in[4];
    const float* time1_w    = (const float*)d_in[5];
    const float* time1_b    = (const float*)d_in[6];
    const float* time2_w    = (const float*)d_in[7];
    const float* time2_b    = (const float*)d_in[8];
    const float* n1_g       = (const float*)d_in[9];
    const float* n1_b       = (const float*)d_in[10];
    const float* n2_g       = (const float*)d_in[11];
    const float* n2_b       = (const float*)d_in[12];
    const float* wq         = (const float*)d_in[13];
    const float* wkv        = (const float*)d_in[14];
    const float* wo         = (const float*)d_in[15];
    const float* ff_g       = (const float*)d_in[16];
    const float* ff_b       = (const float*)d_in[17];
    const float* ff_w1      = (const float*)d_in[18];
    const float* ff_w2      = (const float*)d_in[19];
    const float* ada_w      = (const float*)d_in[20];
    const float* ada_b      = (const float*)d_in[21];
    const float* proj_out_w = (const float*)d_in[22];
    const float* proj_out_b = (const float*)d_in[23];
    const float* out_g      = (const float*)d_in[24];
    const float* out_b      = (const float*)d_in[25];

    float *p_h, *p_lat, *p_qkv, *p_ada8, *p_obuf, *p_part, *p_uu;
    bf16 *p_xs, *p_hns, *p_latms, *p_attns, *p_ffs, *p_lats, *p_stembs, *p_psp, *p_wspl, *p_hnT;
    bf16 *pw_pi, *pw_po, *pw_qkvl, *pw_o, *pw_ada, *pw_f1, *pw_f2;
    cudaGetSymbolAddress((void**)&p_h,      g_h);
    cudaGetSymbolAddress((void**)&p_lat,    g_lat);
    cudaGetSymbolAddress((void**)&p_qkv,    g_qkv);
    cudaGetSymbolAddress((void**)&p_ada8,   g_ada8);
    cudaGetSymbolAddress((void**)&p_obuf,   g_obuf);
    cudaGetSymbolAddress((void**)&p_part,   g_part);
    cudaGetSymbolAddress((void**)&p_uu,     g_uu);
    cudaGetSymbolAddress((void**)&p_xs,     g_xs);
    cudaGetSymbolAddress((void**)&p_hns,    g_hns);
    cudaGetSymbolAddress((void**)&p_latms,  g_latms);
    cudaGetSymbolAddress((void**)&p_attns,  g_attns);
    cudaGetSymbolAddress((void**)&p_ffs,    g_ffs);
    cudaGetSymbolAddress((void**)&p_lats,   g_lats);
    cudaGetSymbolAddress((void**)&p_stembs, g_stembs);
    cudaGetSymbolAddress((void**)&p_psp,    g_psp);
    cudaGetSymbolAddress((void**)&p_wspl,   g_wspl);
    cudaGetSymbolAddress((void**)&p_hnT,    g_hnT);
    cudaGetSymbolAddress((void**)&pw_pi,    w_pi);
    cudaGetSymbolAddress((void**)&pw_po,    w_po);
    cudaGetSymbolAddress((void**)&pw_qkvl,  w_qkvl);
    cudaGetSymbolAddress((void**)&pw_o,     w_o);
    cudaGetSymbolAddress((void**)&pw_ada,   w_ada);
    cudaGetSymbolAddress((void**)&pw_f1,    w_f1);
    cudaGetSymbolAddress((void**)&pw_f2,    w_f2);
    s_part = p_part;

    cudaFuncSetAttribute(gemm_mma, cudaFuncAttributeMaxDynamicSharedMemorySize, GEMM_SMEM);
    cudaFuncSetAttribute(gemm_bat, cudaFuncAttributeMaxDynamicSharedMemorySize, GEMM_SMEM);
    cudaFuncSetAttribute(gemm_s32, cudaFuncAttributeMaxDynamicSharedMemorySize, S32_SMEM);

    // forked stream + events (created once; identical captured work every call)
    static cudaStream_t s2 = nullptr;
    static cudaEvent_t evF = nullptr, evA = nullptr, evQ = nullptr, evR = nullptr;
    if (s2 == nullptr) {
        cudaStreamCreateWithFlags(&s2, cudaStreamNonBlocking);
        cudaEventCreateWithFlags(&evF, cudaEventDisableTiming);
        cudaEventCreateWithFlags(&evA, cudaEventDisableTiming);
        cudaEventCreateWithFlags(&evQ, cudaEventDisableTiming);
        cudaEventCreateWithFlags(&evR, cudaEventDisableTiming);
    }

    // ---- prologue (main stream): pieces the x-path needs ----------------------
    time_mlp_kernel<<<BATCH, 1024>>>(ts, time1_w, time1_b, time2_w, time2_b);
    lat_init_kernel<<<(ML * DIM) / 256, 256>>>(latents);
    wsplit_t<<<dim3(32, 12, 1), 256>>>(proj_in_w, pw_pi, 768, 1024, 0, 0);
    convert_a<<<(int)(((size_t)MX * 768) / 1024), 256>>>(x, p_xs, 768);

    // ---- fork: weight conversions on s2, ordered by first consumption ---------
    cudaEventRecord(evF, 0);
    cudaStreamWaitEvent(s2, evF, 0);
    wsplit_t<<<dim3(128, 16, 8), 256, 0, s2>>>(ada_w, pw_ada, 1024, 4096, (size_t)1024*4096, (size_t)4096*2048);
    cudaEventRecord(evA, s2);
    wsplit_t<<<dim3(32, 16, 8),  256, 0, s2>>>(wq,  pw_qkvl,                     1024, 1024, (size_t)1024*1024, (size_t)3072*2048);
    wsplit_t<<<dim3(64, 16, 8),  256, 0, s2>>>(wkv, pw_qkvl + (size_t)1024*2048, 1024, 2048, (size_t)1024*2048, (size_t)3072*2048);
    cudaEventRecord(evQ, s2);
    wsplit_t<<<dim3(32, 16, 8),  256, 0, s2>>>(wo,    pw_o,   1024, 1024, (size_t)1024*1024, (size_t)1024*2048);
    wsplit_t<<<dim3(128, 16, 8), 256, 0, s2>>>(ff_w1, pw_f1,  1024, 4096, (size_t)1024*4096, (size_t)4096*2048);
    wsplit_t<<<dim3(32, 64, 8),  256, 0, s2>>>(ff_w2, pw_f2,  4096, 1024, (size_t)4096*1024, (size_t)1024*8192);
    wsplit_t<<<dim3(32, 16, 1),  256, 0, s2>>>(proj_out_w, pw_po, 1024, 1024, 0, 0);
    cudaEventRecord(evR, s2);

    // ---- x-path on main stream (overlaps with s2 conversions) -----------------
    gemm_raw(p_xs, pw_pi, nullptr, p_h, MX, DIM, 768, 1, 0, 0);
    ln_h_kernel<<<MX, 256>>>(proj_in_b);
    hnt_kernel<<<dim3(NPAD / 32, 32, BATCH), 256>>>();

    // ---- join 1: ada weights ready -> ada GEMM --------------------------------
    cudaStreamWaitEvent(0, evA, 0);
    {
        gemm_s32<<<dim3((8 * 4096) / 128, 1, 4), 256, S32_SMEM>>>(
            p_stembs, pw_ada, s_part, 8 * 4096, DIM, 12);
        int MN4 = (BATCH * 8 * 4096) / 4;
        reduce_ep4<<<(MN4 + 255) / 256, 256>>>(s_part, ada_b, p_ada8, nullptr,
                                               MN4, 8 * 4096, 4, 0, 0);
    }

    // initial modulated LN for layer 0
    ln_mod_kernel<<<ML, 256>>>(p_lat, nullptr, p_latms, n2_g, n2_b,
                               p_ada8, ADALD, 0, DIM);

    // ---- join 2: qkv weights ready -> layer loop -------------------------------
    cudaStreamWaitEvent(0, evQ, 0);

    for (int i = 0; i < 8; i++) {
        const float* wkv_i = wkv + (size_t)i * 1024 * 2048;
        const float* n1g_i = n1_g + i * DIM;
        const float* n1b_i = n1_b + i * DIM;

        // fused q + latent kv: [256, 3072]
        gemm(p_latms, pw_qkvl + (size_t)i*3072*2048, nullptr, p_qkv, nullptr,
             ML, 3072, DIM, 6, 0, 0);

        pproj_kernel<<<BATCH * HEADS, 256>>>(wkv_i, n1g_i, n1b_i);

        // token scores (0..255): P' @ hn^T, segments -> 3 partial planes
        gemm_bat<<<dim3(2, 3, BATCH), 256, GEMM_SMEM>>>(
            p_psp, p_hns, p_part, 256, 1024, 256,
            (size_t)128*2048, (size_t)TOK*2048, (size_t)128*256, SEG_S);

        softmax_kernel<<<BATCH * HEADS, 256>>>();

        // U = W @ hn over tokens 0..255 (token 256 rank-1 in oproj)
        gemm_bat<<<dim3(8, 1, BATCH), 256, GEMM_SMEM>>>(
            p_wspl, p_hnT, p_uu, 1024, NPAD, 1024,
            (size_t)128*(2*NPAD), (size_t)1024*(2*NPAD), (size_t)128*1024, 0);

        oproj_kernel<<<BATCH * HEADS, 256>>>(wkv_i, n1g_i, n1b_i);

        // join 3 (layer 0 only): wo/f1/f2/po weights ready
        if (i == 0) cudaStreamWaitEvent(0, evR, 0);

        // wo projection -> partials; fused reduce + residual + ff-LN -> latms
        gemm_raw(p_attns, pw_o + (size_t)i*1024*2048, nullptr, nullptr,
                 ML, DIM, DIM, 16, 0, 0);
        reduce_ln<<<ML, 256>>>(s_part, 16, p_lat, p_latms,
                               ff_g + i*DIM, ff_b + i*DIM,
                               p_ada8 + (size_t)i*4096, 2*DIM, 3*DIM);

        // FF
        gemm(p_latms, pw_f1 + (size_t)i*4096*2048, nullptr, nullptr, p_ffs,
             ML, FFI, DIM, 8, 1, 0);
        gemm_raw(p_ffs, pw_f2 + (size_t)i*1024*8192, nullptr, nullptr,
                 ML, DIM, FFI, 16, 0, 0);
        if (i < 7)
            reduce_ln<<<ML, 256>>>(s_part, 16, p_lat, p_latms,
                                   n2_g + (i+1)*DIM, n2_b + (i+1)*DIM,
                                   p_ada8 + (size_t)(i+1)*4096, 0, DIM);
        else
            reduce_ln<<<ML, 256>>>(s_part, 16, p_lat, p_lats,
                                   nullptr, nullptr, nullptr, 0, 0);
    }

    gemm(p_lats, pw_po, proj_out_b, p_obuf, nullptr, ML, DIM, DIM, 16, 0, 0);
    ln_mod_kernel<<<ML, 256>>>(p_obuf, (float*)d_out, nullptr, out_g, out_b,
                               nullptr, 0, 0, 0);
}